// round 2
// baseline (speedup 1.0000x reference)
#include <cuda_runtime.h>
#include <math.h>

#define PS    16
#define HID   8
#define GRIDP 24
#define NPATCH 576      // 24*24
#define NB    2
#define HW    384
#define DIN   256
#define KVSTR 9         // padded K/V row stride (coprime with 32 banks)
#define SCALE 0.35355339059327373f

// ---------------- scratch (device globals; no allocation allowed) ----------
__device__ float g_q1[NB*NPATCH*HID];
__device__ float g_k1[NB*NPATCH*HID];
__device__ float g_v1[NB*NPATCH*HID];
__device__ float g_q2[NB*NPATCH*HID];
__device__ float g_k2[NB*NPATCH*HID];
__device__ float g_v2[NB*NPATCH*HID];
__device__ float g_s [NB*NPATCH*3];
__device__ int   g_max;

// ---------------- init -----------------------------------------------------
__global__ void init_kernel() { g_max = 0; }

// ---------------- patch unfold + QKV projection (256 -> 8, x3) -------------
// grid (576, 2), 256 threads. Warp w computes output column w of Q,K,V.
__global__ void qkv_kernel(const float* __restrict__ x,
                           const float* __restrict__ Wq, const float* __restrict__ bq,
                           const float* __restrict__ Wk, const float* __restrict__ bk,
                           const float* __restrict__ Wv, const float* __restrict__ bv) {
    __shared__ float pat[DIN];
    const int n = blockIdx.x, b = blockIdx.y;
    const int hp = n / GRIDP, wn = n % GRIDP;
    const int tid = threadIdx.x;
    const int r = tid >> 4, cc = tid & 15;
    pat[tid] = x[(b*HW + hp*PS + r)*HW + wn*PS + cc];
    __syncthreads();
    const int w = tid >> 5, lane = tid & 31;
    float aq = 0.f, ak = 0.f, av = 0.f;
    #pragma unroll
    for (int it = 0; it < DIN/32; ++it) {
        int i = lane + 32*it;
        float p = pat[i];
        aq = fmaf(p, Wq[i*HID + w], aq);
        ak = fmaf(p, Wk[i*HID + w], ak);
        av = fmaf(p, Wv[i*HID + w], av);
    }
    #pragma unroll
    for (int o = 16; o; o >>= 1) {
        aq += __shfl_xor_sync(0xffffffffu, aq, o);
        ak += __shfl_xor_sync(0xffffffffu, ak, o);
        av += __shfl_xor_sync(0xffffffffu, av, o);
    }
    if (lane == 0) {
        int base = (b*NPATCH + n)*HID + w;
        g_q1[base] = aq + bq[w];
        g_k1[base] = ak + bk[w];
        g_v1[base] = av + bv[w];
    }
}

// ---------------- attention 1 (+ project to q2/k2/v2) ----------------------
// grid (72, 2), 256 threads (8 warps). Warp = one query; lanes split keys.
__global__ void attn1_kernel(const float* __restrict__ Wsq, const float* __restrict__ bsq,
                             const float* __restrict__ Wsk, const float* __restrict__ bsk,
                             const float* __restrict__ Wsv, const float* __restrict__ bsv) {
    __shared__ float Ks[NPATCH*KVSTR];
    __shared__ float Vs[NPATCH*KVSTR];
    const int b = blockIdx.y;
    const int tid = threadIdx.x;
    const float* kb = g_k1 + b*NPATCH*HID;
    const float* vb = g_v1 + b*NPATCH*HID;
    for (int i = tid; i < NPATCH*HID; i += 256) {
        int m = i >> 3, j = i & 7;
        Ks[m*KVSTR + j] = kb[i];
        Vs[m*KVSTR + j] = vb[i];
    }
    __syncthreads();
    const int w = tid >> 5, lane = tid & 31;
    const int qi = blockIdx.x * 8 + w;
    const float* qp = g_q1 + (b*NPATCH + qi)*HID;
    float q[HID];
    #pragma unroll
    for (int j = 0; j < HID; j++) q[j] = qp[j] * SCALE;
    float sum = 0.f, acc[HID];
    #pragma unroll
    for (int j = 0; j < HID; j++) acc[j] = 0.f;
    for (int m = lane; m < NPATCH; m += 32) {
        const float* kr = Ks + m*KVSTR;
        float s = 0.f;
        #pragma unroll
        for (int j = 0; j < HID; j++) s = fmaf(q[j], kr[j], s);
        float e = __expf(s);
        sum += e;
        const float* vr = Vs + m*KVSTR;
        #pragma unroll
        for (int j = 0; j < HID; j++) acc[j] = fmaf(e, vr[j], acc[j]);
    }
    #pragma unroll
    for (int o = 16; o; o >>= 1) {
        sum += __shfl_xor_sync(0xffffffffu, sum, o);
        #pragma unroll
        for (int j = 0; j < HID; j++) acc[j] += __shfl_xor_sync(0xffffffffu, acc[j], o);
    }
    const float inv = 1.f / sum;
    float fo[HID];
    #pragma unroll
    for (int j = 0; j < HID; j++) fo[j] = acc[j] * inv;
    if (lane < HID) {
        float q2 = bsq[lane], k2 = bsk[lane], v2 = bsv[lane];
        #pragma unroll
        for (int i = 0; i < HID; i++) {
            q2 = fmaf(fo[i], Wsq[i*HID + lane], q2);
            k2 = fmaf(fo[i], Wsk[i*HID + lane], k2);
            v2 = fmaf(fo[i], Wsv[i*HID + lane], v2);
        }
        int base = (b*NPATCH + qi)*HID + lane;
        g_q2[base] = q2; g_k2[base] = k2; g_v2[base] = v2;
    }
}

// ---------------- attention 2 + layernorm + sigma head ----------------------
__global__ void attn2_kernel(const float* __restrict__ ln_g, const float* __restrict__ ln_b,
                             const float* __restrict__ Wp,   const float* __restrict__ bp) {
    __shared__ float Ks[NPATCH*KVSTR];
    __shared__ float Vs[NPATCH*KVSTR];
    const int b = blockIdx.y;
    const int tid = threadIdx.x;
    const float* kb = g_k2 + b*NPATCH*HID;
    const float* vb = g_v2 + b*NPATCH*HID;
    for (int i = tid; i < NPATCH*HID; i += 256) {
        int m = i >> 3, j = i & 7;
        Ks[m*KVSTR + j] = kb[i];
        Vs[m*KVSTR + j] = vb[i];
    }
    __syncthreads();
    const int w = tid >> 5, lane = tid & 31;
    const int qi = blockIdx.x * 8 + w;
    const float* qp = g_q2 + (b*NPATCH + qi)*HID;
    float q[HID];
    #pragma unroll
    for (int j = 0; j < HID; j++) q[j] = qp[j] * SCALE;
    float sum = 0.f, acc[HID];
    #pragma unroll
    for (int j = 0; j < HID; j++) acc[j] = 0.f;
    for (int m = lane; m < NPATCH; m += 32) {
        const float* kr = Ks + m*KVSTR;
        float s = 0.f;
        #pragma unroll
        for (int j = 0; j < HID; j++) s = fmaf(q[j], kr[j], s);
        float e = __expf(s);
        sum += e;
        const float* vr = Vs + m*KVSTR;
        #pragma unroll
        for (int j = 0; j < HID; j++) acc[j] = fmaf(e, vr[j], acc[j]);
    }
    #pragma unroll
    for (int o = 16; o; o >>= 1) {
        sum += __shfl_xor_sync(0xffffffffu, sum, o);
        #pragma unroll
        for (int j = 0; j < HID; j++) acc[j] += __shfl_xor_sync(0xffffffffu, acc[j], o);
    }
    const float inv = 1.f / sum;
    float fo[HID];
    #pragma unroll
    for (int j = 0; j < HID; j++) fo[j] = acc[j] * inv;
    // layernorm over HID (every lane redundantly)
    float mu = 0.f;
    #pragma unroll
    for (int j = 0; j < HID; j++) mu += fo[j];
    mu *= 0.125f;
    float var = 0.f;
    #pragma unroll
    for (int j = 0; j < HID; j++) { float d = fo[j] - mu; var = fmaf(d, d, var); }
    var *= 0.125f;
    const float rstd = rsqrtf(var + 1e-5f);
    float oin[HID];
    #pragma unroll
    for (int j = 0; j < HID; j++)
        oin[j] = (fo[j] - mu) * rstd * ln_g[j] + ln_b[j];
    if (lane < 3) {
        float sv = bp[lane];
        #pragma unroll
        for (int i = 0; i < HID; i++) sv = fmaf(oin[i], Wp[i*3 + lane], sv);
        float spv = (sv > 20.f) ? sv : log1pf(expf(sv));       // softplus
        float sig = fminf(spv, 6.0f) + 1e-6f;                  // BoundedSoftplus
        g_s[(b*NPATCH + qi)*3 + lane] = sig;
        if (lane < 2) atomicMax(&g_max, __float_as_int(sig));  // positive floats: int order ok
    }
}

// ---------------- bilateral filter ------------------------------------------
// grid (576, 2), 256 threads = one 16x16 patch per block (constant sigmas).
__global__ void bilateral_kernel(const float* __restrict__ x, float* __restrict__ out) {
    __shared__ float tile[32*32];      // stride 32 -> conflict-free half-warp rows
    __shared__ float sp[17*17];        // spatial kernel (k <= 17 since sigma cap = 6)
    const int n = blockIdx.x, b = blockIdx.y;
    const int hp = n / GRIDP, wn = n % GRIDP;
    const int tid = threadIdx.x;

    const float m = __int_as_float(g_max);
    const int half = (int)ceilf(m + 1.0f);
    const int k = 2*half + 1;
    const int T = PS + 2*half;

    const float* sv = g_s + (b*NPATCH + n)*3;
    const float sx = sv[0], sy = sv[1], sr = sv[2];
    const float ix = -0.5f/(sx*sx), iy = -0.5f/(sy*sy), ir = -0.5f/(sr*sr);

    const int y0 = hp*PS - half, x0 = wn*PS - half;
    const float* xb = x + b*HW*HW;
    for (int i = tid; i < T*T; i += 256) {
        int ty = i / T, tx = i - ty*T;
        int gy = y0 + ty, gx = x0 + tx;
        float v = 0.f;
        if ((unsigned)gy < HW && (unsigned)gx < HW) v = xb[gy*HW + gx];
        tile[ty*32 + tx] = v;
    }
    const int kk = k*k;
    for (int t = tid; t < kk; t += 256) {
        int dy = t / k, dx = t - dy*k;
        float fx = (float)(dx - half), fy = (float)(dy - half);
        sp[t] = __expf(fx*fx*ix + fy*fy*iy);
    }
    __syncthreads();

    const int r = tid >> 4, cc = tid & 15;
    const float c = tile[(r + half)*32 + cc + half];
    float acc = 0.f, wsum = 0.f;
    for (int dy = 0; dy < k; dy++) {
        const float* trow  = tile + (r + dy)*32 + cc;
        const float* sprow = sp + dy*k;
        #pragma unroll 4
        for (int dx = 0; dx < k; dx++) {
            float p = trow[dx];
            float d = c - p;
            float w = sprow[dx] * __expf(d*d*ir);
            wsum += w;
            acc = fmaf(w, p, acc);
        }
    }
    out[(b*HW + hp*PS + r)*HW + wn*PS + cc] = acc / (wsum + 1e-8f);
}

// ---------------- launcher ---------------------------------------------------
extern "C" void kernel_launch(void* const* d_in, const int* in_sizes, int n_in,
                              void* d_out, int out_size) {
    const float* x    = (const float*)d_in[0];
    const float* Wq   = (const float*)d_in[1];
    const float* bq   = (const float*)d_in[2];
    const float* Wk   = (const float*)d_in[3];
    const float* bk   = (const float*)d_in[4];
    const float* Wv   = (const float*)d_in[5];
    const float* bv   = (const float*)d_in[6];
    const float* Wsq  = (const float*)d_in[7];
    const float* bsq  = (const float*)d_in[8];
    const float* Wsk  = (const float*)d_in[9];
    const float* bsk  = (const float*)d_in[10];
    const float* Wsv  = (const float*)d_in[11];
    const float* bsv  = (const float*)d_in[12];
    const float* ln_g = (const float*)d_in[13];
    const float* ln_b = (const float*)d_in[14];
    const float* Wp   = (const float*)d_in[15];
    const float* bp   = (const float*)d_in[16];
    float* out = (float*)d_out;

    init_kernel<<<1, 1>>>();
    qkv_kernel<<<dim3(NPATCH, NB), 256>>>(x, Wq, bq, Wk, bk, Wv, bv);
    attn1_kernel<<<dim3(NPATCH/8, NB), 256>>>(Wsq, bsq, Wsk, bsk, Wsv, bsv);
    attn2_kernel<<<dim3(NPATCH/8, NB), 256>>>(ln_g, ln_b, Wp, bp);
    bilateral_kernel<<<dim3(NPATCH, NB), 256>>>(x, out);
}

// round 4
// speedup vs baseline: 1.2058x; 1.2058x over previous
#include <cuda_runtime.h>
#include <math.h>

#define PS    16
#define HID   8
#define GRIDP 24
#define NPATCH 576      // 24*24
#define NB    2
#define HW    384
#define DIN   256
#define SPLITS 6        // 96 keys per split = 3 per lane
#define SCALE 0.35355339059327373f

typedef unsigned long long u64;

// ---------------- scratch (device globals; no allocation allowed) ----------
__device__ float g_q1[NB*NPATCH*HID];
__device__ float g_k1[NB*NPATCH*HID];
__device__ float g_v1[NB*NPATCH*HID];
__device__ float g_q2[NB*NPATCH*HID];
__device__ float g_k2[NB*NPATCH*HID];
__device__ float g_v2[NB*NPATCH*HID];
__device__ float g_part[NB*SPLITS*NPATCH*12];   // [acc0..7, sum, pad..]
__device__ float g_s [NB*NPATCH*3];
__device__ int   g_max;

// ---------------- packed f32x2 helpers (Blackwell) --------------------------
__device__ __forceinline__ u64 pk2(float lo, float hi){
    u64 r; asm("mov.b64 %0, {%1, %2};" : "=l"(r) : "f"(lo), "f"(hi)); return r;
}
__device__ __forceinline__ float2 upk2(u64 v){
    float2 f; asm("mov.b64 {%0, %1}, %2;" : "=f"(f.x), "=f"(f.y) : "l"(v)); return f;
}
__device__ __forceinline__ u64 fma2_(u64 a, u64 b, u64 c){
    u64 d; asm("fma.rn.f32x2 %0, %1, %2, %3;" : "=l"(d) : "l"(a), "l"(b), "l"(c)); return d;
}
__device__ __forceinline__ u64 mul2_(u64 a, u64 b){
    u64 d; asm("mul.rn.f32x2 %0, %1, %2;" : "=l"(d) : "l"(a), "l"(b)); return d;
}
__device__ __forceinline__ u64 add2_(u64 a, u64 b){
    u64 d; asm("add.rn.f32x2 %0, %1, %2;" : "=l"(d) : "l"(a), "l"(b)); return d;
}

// ---------------- patch unfold + QKV projection (256 -> 8, x3) -------------
__global__ void qkv_kernel(const float* __restrict__ x,
                           const float* __restrict__ Wq, const float* __restrict__ bq,
                           const float* __restrict__ Wk, const float* __restrict__ bk,
                           const float* __restrict__ Wv, const float* __restrict__ bv) {
    __shared__ float pat[DIN];
    const int n = blockIdx.x, b = blockIdx.y;
    if (n == 0 && b == 0 && threadIdx.x == 0) g_max = 0;   // fold init
    const int hp = n / GRIDP, wn = n % GRIDP;
    const int tid = threadIdx.x;
    const int r = tid >> 4, cc = tid & 15;
    pat[tid] = x[(b*HW + hp*PS + r)*HW + wn*PS + cc];
    __syncthreads();
    const int w = tid >> 5, lane = tid & 31;
    float aq = 0.f, ak = 0.f, av = 0.f;
    #pragma unroll
    for (int it = 0; it < DIN/32; ++it) {
        int i = lane + 32*it;
        float p = pat[i];
        aq = fmaf(p, Wq[i*HID + w], aq);
        ak = fmaf(p, Wk[i*HID + w], ak);
        av = fmaf(p, Wv[i*HID + w], av);
    }
    #pragma unroll
    for (int o = 16; o; o >>= 1) {
        aq += __shfl_xor_sync(0xffffffffu, aq, o);
        ak += __shfl_xor_sync(0xffffffffu, ak, o);
        av += __shfl_xor_sync(0xffffffffu, av, o);
    }
    if (lane == 0) {
        int base = (b*NPATCH + n)*HID + w;
        g_q1[base] = aq + bq[w];
        g_k1[base] = ak + bk[w];
        g_v1[base] = av + bv[w];
    }
}

// ---------------- attention partial: grid (72, SPLITS, NB), 256 threads -----
// warp = one query; lane handles 3 keys of this split; no smem, direct L2.
__global__ void attn_part_kernel(int stage) {
    const float* Q = stage ? g_q2 : g_q1;
    const float* K = stage ? g_k2 : g_k1;
    const float* V = stage ? g_v2 : g_v1;
    const int b = blockIdx.z, s = blockIdx.y;
    const int w = threadIdx.x >> 5, lane = threadIdx.x & 31;
    const int qi = blockIdx.x * 8 + w;
    const float4* q4 = (const float4*)(Q + (b*NPATCH + qi)*HID);
    float4 qa = q4[0], qb = q4[1];
    qa.x *= SCALE; qa.y *= SCALE; qa.z *= SCALE; qa.w *= SCALE;
    qb.x *= SCALE; qb.y *= SCALE; qb.z *= SCALE; qb.w *= SCALE;

    float sum = 0.f;
    float4 A = {0,0,0,0}, B = {0,0,0,0};
    #pragma unroll
    for (int t = 0; t < 3; t++) {
        const int m = s*96 + lane + 32*t;
        const float4* k4 = (const float4*)(K + (b*NPATCH + m)*HID);
        float4 ka = k4[0], kb = k4[1];
        float d = qa.x*ka.x;
        d = fmaf(qa.y, ka.y, d); d = fmaf(qa.z, ka.z, d); d = fmaf(qa.w, ka.w, d);
        d = fmaf(qb.x, kb.x, d); d = fmaf(qb.y, kb.y, d);
        d = fmaf(qb.z, kb.z, d); d = fmaf(qb.w, kb.w, d);
        float e = __expf(d);
        sum += e;
        const float4* v4 = (const float4*)(V + (b*NPATCH + m)*HID);
        float4 va = v4[0], vb = v4[1];
        A.x = fmaf(e, va.x, A.x); A.y = fmaf(e, va.y, A.y);
        A.z = fmaf(e, va.z, A.z); A.w = fmaf(e, va.w, A.w);
        B.x = fmaf(e, vb.x, B.x); B.y = fmaf(e, vb.y, B.y);
        B.z = fmaf(e, vb.z, B.z); B.w = fmaf(e, vb.w, B.w);
    }
    #pragma unroll
    for (int o = 16; o; o >>= 1) {
        sum += __shfl_xor_sync(0xffffffffu, sum, o);
        A.x += __shfl_xor_sync(0xffffffffu, A.x, o);
        A.y += __shfl_xor_sync(0xffffffffu, A.y, o);
        A.z += __shfl_xor_sync(0xffffffffu, A.z, o);
        A.w += __shfl_xor_sync(0xffffffffu, A.w, o);
        B.x += __shfl_xor_sync(0xffffffffu, B.x, o);
        B.y += __shfl_xor_sync(0xffffffffu, B.y, o);
        B.z += __shfl_xor_sync(0xffffffffu, B.z, o);
        B.w += __shfl_xor_sync(0xffffffffu, B.w, o);
    }
    if (lane == 0) {
        float* p = g_part + ((b*SPLITS + s)*NPATCH + qi)*12;
        ((float4*)p)[0] = A;
        ((float4*)p)[1] = B;
        p[8] = sum;
    }
}

// ---------------- finalize helpers ------------------------------------------
__device__ __forceinline__ void gather_fo(int b, int q, float fo[HID]) {
    float acc[HID];
    #pragma unroll
    for (int j = 0; j < HID; j++) acc[j] = 0.f;
    float sum = 0.f;
    #pragma unroll
    for (int s = 0; s < SPLITS; s++) {
        const float* p = g_part + ((b*SPLITS + s)*NPATCH + q)*12;
        float4 A = ((const float4*)p)[0];
        float4 B = ((const float4*)p)[1];
        acc[0]+=A.x; acc[1]+=A.y; acc[2]+=A.z; acc[3]+=A.w;
        acc[4]+=B.x; acc[5]+=B.y; acc[6]+=B.z; acc[7]+=B.w;
        sum += p[8];
    }
    const float inv = 1.f / sum;
    #pragma unroll
    for (int j = 0; j < HID; j++) fo[j] = acc[j]*inv;
}

// finalize stage 1: fo -> q2/k2/v2. 1 thread per query.
__global__ void fin1_kernel(const float* __restrict__ Wsq, const float* __restrict__ bsq,
                            const float* __restrict__ Wsk, const float* __restrict__ bsk,
                            const float* __restrict__ Wsv, const float* __restrict__ bsv) {
    const int t = blockIdx.x*256 + threadIdx.x;
    if (t >= NB*NPATCH) return;
    const int b = t / NPATCH, q = t % NPATCH;
    float fo[HID];
    gather_fo(b, q, fo);
    float q2[HID], k2[HID], v2[HID];
    #pragma unroll
    for (int j = 0; j < HID; j++) { q2[j] = bsq[j]; k2[j] = bsk[j]; v2[j] = bsv[j]; }
    #pragma unroll
    for (int i = 0; i < HID; i++) {
        const float f = fo[i];
        #pragma unroll
        for (int j = 0; j < HID; j++) {
            q2[j] = fmaf(f, Wsq[i*HID + j], q2[j]);
            k2[j] = fmaf(f, Wsk[i*HID + j], k2[j]);
            v2[j] = fmaf(f, Wsv[i*HID + j], v2[j]);
        }
    }
    float* oq = g_q2 + t*HID; float* ok = g_k2 + t*HID; float* ov = g_v2 + t*HID;
    ((float4*)oq)[0] = make_float4(q2[0],q2[1],q2[2],q2[3]);
    ((float4*)oq)[1] = make_float4(q2[4],q2[5],q2[6],q2[7]);
    ((float4*)ok)[0] = make_float4(k2[0],k2[1],k2[2],k2[3]);
    ((float4*)ok)[1] = make_float4(k2[4],k2[5],k2[6],k2[7]);
    ((float4*)ov)[0] = make_float4(v2[0],v2[1],v2[2],v2[3]);
    ((float4*)ov)[1] = make_float4(v2[4],v2[5],v2[6],v2[7]);
}

// finalize stage 2: fo -> layernorm -> sigma head -> g_s + g_max.
__global__ void fin2_kernel(const float* __restrict__ ln_g, const float* __restrict__ ln_b,
                            const float* __restrict__ Wp,   const float* __restrict__ bp) {
    const int t = blockIdx.x*256 + threadIdx.x;
    if (t >= NB*NPATCH) return;
    const int b = t / NPATCH, q = t % NPATCH;
    float fo[HID];
    gather_fo(b, q, fo);
    float mu = 0.f;
    #pragma unroll
    for (int j = 0; j < HID; j++) mu += fo[j];
    mu *= 0.125f;
    float var = 0.f;
    #pragma unroll
    for (int j = 0; j < HID; j++) { float d = fo[j]-mu; var = fmaf(d,d,var); }
    var *= 0.125f;
    const float rstd = rsqrtf(var + 1e-5f);
    float oin[HID];
    #pragma unroll
    for (int j = 0; j < HID; j++) oin[j] = (fo[j]-mu)*rstd*ln_g[j] + ln_b[j];
    float sig[3];
    #pragma unroll
    for (int j = 0; j < 3; j++) {
        float sv = bp[j];
        #pragma unroll
        for (int i = 0; i < HID; i++) sv = fmaf(oin[i], Wp[i*3 + j], sv);
        float spv = (sv > 20.f) ? sv : log1pf(expf(sv));
        sig[j] = fminf(spv, 6.0f) + 1e-6f;
        g_s[(b*NPATCH + q)*3 + j] = sig[j];
    }
    const float mx = fmaxf(sig[0], sig[1]);
    atomicMax(&g_max, __float_as_int(mx));   // positive floats: int order ok
}

// ---------------- bilateral core (templated, f32x2 packed) -------------------
template<int K>
__device__ __forceinline__ float bilat_core(const float* tb, const float* spP,
                                            int r, float c, u64 C1, u64 C2, u64 C3) {
    constexpr int KE = K + 1, KE2 = KE/2;
    const u64 c2   = pk2(c, c);
    const u64 NEG1 = pk2(-1.f, -1.f);
    const u64 ONE2 = pk2(1.f, 1.f);
    u64 ws = 0ull, ac = 0ull;        // bit pattern of (0.f, 0.f)
    #pragma unroll
    for (int dy = 0; dy < K; dy++) {
        const u64* trow = (const u64*)(tb + (r + dy)*32);
        const u64* srow = (const u64*)(spP + dy*KE);
        #pragma unroll
        for (int j = 0; j < KE2; j++) {
            u64 p2 = trow[j];
            u64 s2 = srow[j];
            u64 d2 = fma2_(p2, NEG1, c2);        // c - p
            u64 dd = mul2_(d2, d2);
            u64 t2 = fma2_(dd, C3, C2);
            t2     = fma2_(dd, t2, C1);
            u64 rg = fma2_(dd, t2, ONE2);        // ~exp(dd*ir), 3rd-order
            u64 w2 = mul2_(s2, rg);
            ws     = add2_(ws, w2);
            ac     = fma2_(w2, p2, ac);
        }
    }
    float2 w = upk2(ws), a = upk2(ac);
    return (a.x + a.y) / ((w.x + w.y) + 1e-8f);
}

// ---------------- bilateral filter ------------------------------------------
// grid (576, 2), 256 threads = one 16x16 patch (constant sigmas per patch).
__global__ void bilateral_kernel(const float* __restrict__ x, float* __restrict__ out) {
    __shared__ __align__(16) float tE[1056];   // tile, stride 32
    __shared__ __align__(16) float tO[1056];   // tO[i] = tile[i+1] (odd-parity copy)
    __shared__ __align__(16) float spP[324];   // spatial table, stride kE (even)
    const int n = blockIdx.x, b = blockIdx.y;
    const int hp = n / GRIDP, wn = n % GRIDP;
    const int tid = threadIdx.x;

    const float m = __int_as_float(g_max);
    const int half = (int)ceilf(m + 1.0f);
    const int k = 2*half + 1, kE = k + 1;

    const float* sv = g_s + (b*NPATCH + n)*3;
    const float sx = sv[0], sy = sv[1], sr = sv[2];
    const float ix = -0.5f/(sx*sx), iy = -0.5f/(sy*sy), ir = -0.5f/(sr*sr);
    const float c1 = ir, c2c = 0.5f*ir*ir, c3c = ir*ir*ir*(1.f/6.f);
    const u64 C1 = pk2(c1,c1), C2 = pk2(c2c,c2c), C3 = pk2(c3c,c3c);

    const int y0 = hp*PS - half, x0 = wn*PS - half;
    const float* xb = x + b*HW*HW;
    for (int i = tid; i < 1056; i += 256) {
        int ty = i >> 5, tx = i & 31;
        int gy = y0 + ty, gx = x0 + tx;
        float v = 0.f;
        if ((unsigned)gy < HW && (unsigned)gx < HW) v = xb[gy*HW + gx];
        tE[i] = v;
        if (i > 0) tO[i-1] = v;
    }
    const int kkE = k*kE;
    for (int t = tid; t < kkE; t += 256) {
        int dy = t / kE, dx = t - dy*kE;
        float val = 0.f;
        if (dx < k) {
            float fx = (float)(dx - half), fy = (float)(dy - half);
            val = __expf(fx*fx*ix + fy*fy*iy);
        }
        spP[t] = val;
    }
    __syncthreads();

    const int r = tid >> 4, cc = tid & 15;
    const float* tb = (cc & 1) ? (tO + cc - 1) : (tE + cc);
    const float c = tE[(r + half)*32 + cc + half];

    float res;
    switch (k) {
        case 3:  res = bilat_core<3 >(tb, spP, r, c, C1, C2, C3); break;
        case 5:  res = bilat_core<5 >(tb, spP, r, c, C1, C2, C3); break;
        case 7:  res = bilat_core<7 >(tb, spP, r, c, C1, C2, C3); break;
        case 9:  res = bilat_core<9 >(tb, spP, r, c, C1, C2, C3); break;
        case 11: res = bilat_core<11>(tb, spP, r, c, C1, C2, C3); break;
        case 13: res = bilat_core<13>(tb, spP, r, c, C1, C2, C3); break;
        case 15: res = bilat_core<15>(tb, spP, r, c, C1, C2, C3); break;
        case 17: res = bilat_core<17>(tb, spP, r, c, C1, C2, C3); break;
        default: {   // generic fallback (never expected)
            float acc = 0.f, wsum = 0.f;
            for (int dy = 0; dy < k; dy++) {
                const float* trow = tE + (r + dy)*32 + cc;
                const float* srow = spP + dy*kE;
                for (int dx = 0; dx < k; dx++) {
                    float p = trow[dx];
                    float d = c - p;
                    float w = srow[dx] * __expf(d*d*ir);
                    wsum += w;
                    acc = fmaf(w, p, acc);
                }
            }
            res = acc / (wsum + 1e-8f);
        }
    }
    out[(b*HW + hp*PS + r)*HW + wn*PS + cc] = res;
}

// ---------------- launcher ---------------------------------------------------
extern "C" void kernel_launch(void* const* d_in, const int* in_sizes, int n_in,
                              void* d_out, int out_size) {
    const float* x    = (const float*)d_in[0];
    const float* Wq   = (const float*)d_in[1];
    const float* bq   = (const float*)d_in[2];
    const float* Wk   = (const float*)d_in[3];
    const float* bk   = (const float*)d_in[4];
    const float* Wv   = (const float*)d_in[5];
    const float* bv   = (const float*)d_in[6];
    const float* Wsq  = (const float*)d_in[7];
    const float* bsq  = (const float*)d_in[8];
    const float* Wsk  = (const float*)d_in[9];
    const float* bsk  = (const float*)d_in[10];
    const float* Wsv  = (const float*)d_in[11];
    const float* bsv  = (const float*)d_in[12];
    const float* ln_g = (const float*)d_in[13];
    const float* ln_b = (const float*)d_in[14];
    const float* Wp   = (const float*)d_in[15];
    const float* bp   = (const float*)d_in[16];
    float* out = (float*)d_out;

    qkv_kernel<<<dim3(NPATCH, NB), 256>>>(x, Wq, bq, Wk, bk, Wv, bv);
    attn_part_kernel<<<dim3(NPATCH/8, SPLITS, NB), 256>>>(0);
    fin1_kernel<<<(NB*NPATCH + 255)/256, 256>>>(Wsq, bsq, Wsk, bsk, Wsv, bsv);
    attn_part_kernel<<<dim3(NPATCH/8, SPLITS, NB), 256>>>(1);
    fin2_kernel<<<(NB*NPATCH + 255)/256, 256>>>(ln_g, ln_b, Wp, bp);
    bilateral_kernel<<<dim3(NPATCH, NB), 256>>>(x, out);
}

// round 5
// speedup vs baseline: 1.5318x; 1.2704x over previous
#include <cuda_runtime.h>
#include <math.h>

#define PS    16
#define HID   8
#define GRIDP 24
#define NPATCH 576      // 24*24
#define NB    2
#define HW    384
#define DIN   256
#define SPLITS 6        // 96 keys per split
#define SCALE 0.35355339059327373f

typedef unsigned long long u64;

// ---------------- scratch (device globals; no allocation allowed) ----------
__device__ float g_q1[NB*NPATCH*HID];
__device__ float g_k1[NB*NPATCH*HID];
__device__ float g_v1[NB*NPATCH*HID];
__device__ float g_part [NB*SPLITS*NPATCH*12];   // stage-0 partials
__device__ float g_part2[NB*SPLITS*NPATCH*12];   // stage-1 partials
__device__ float g_s [NB*NPATCH*3];
__device__ int   g_max;

// ---------------- packed f32x2 helpers (Blackwell) --------------------------
__device__ __forceinline__ u64 pk2(float lo, float hi){
    u64 r; asm("mov.b64 %0, {%1, %2};" : "=l"(r) : "f"(lo), "f"(hi)); return r;
}
__device__ __forceinline__ float2 upk2(u64 v){
    float2 f; asm("mov.b64 {%0, %1}, %2;" : "=f"(f.x), "=f"(f.y) : "l"(v)); return f;
}
__device__ __forceinline__ u64 fma2_(u64 a, u64 b, u64 c){
    u64 d; asm("fma.rn.f32x2 %0, %1, %2, %3;" : "=l"(d) : "l"(a), "l"(b), "l"(c)); return d;
}
__device__ __forceinline__ u64 mul2_(u64 a, u64 b){
    u64 d; asm("mul.rn.f32x2 %0, %1, %2;" : "=l"(d) : "l"(a), "l"(b)); return d;
}
__device__ __forceinline__ u64 add2_(u64 a, u64 b){
    u64 d; asm("add.rn.f32x2 %0, %1, %2;" : "=l"(d) : "l"(a), "l"(b)); return d;
}

// ---------------- qkv: 4 patches/block, smem-staged transposed W ------------
// grid (144, 2), 256 threads. warp w = output col w; lane over input dim.
__global__ void qkv_kernel(const float* __restrict__ x,
                           const float* __restrict__ Wq, const float* __restrict__ bq,
                           const float* __restrict__ Wk, const float* __restrict__ bk,
                           const float* __restrict__ Wv, const float* __restrict__ bv) {
    __shared__ float sWq[DIN*9], sWk[DIN*9], sWv[DIN*9];   // [i*9 + col], pad 9
    __shared__ float sPat[4][DIN];
    const int n0 = blockIdx.x * 4, b = blockIdx.y;
    const int tid = threadIdx.x;
    if (blockIdx.x == 0 && b == 0 && tid == 0) g_max = 0;  // fold init

    #pragma unroll
    for (int e = tid; e < DIN*HID; e += 256) {
        int idx = (e >> 3)*9 + (e & 7);
        sWq[idx] = Wq[e]; sWk[idx] = Wk[e]; sWv[idx] = Wv[e];
    }
    const int r = tid >> 4, cc = tid & 15;
    #pragma unroll
    for (int p = 0; p < 4; p++) {
        int n = n0 + p;
        int hp = n / GRIDP, wn = n % GRIDP;
        sPat[p][tid] = x[(b*HW + hp*PS + r)*HW + wn*PS + cc];
    }
    __syncthreads();

    const int w = tid >> 5, lane = tid & 31;
    float aq[4] = {0,0,0,0}, ak[4] = {0,0,0,0}, av[4] = {0,0,0,0};
    #pragma unroll
    for (int it = 0; it < DIN/32; ++it) {
        const int i = lane + 32*it;
        const float wq = sWq[i*9 + w], wk = sWk[i*9 + w], wv = sWv[i*9 + w];
        #pragma unroll
        for (int p = 0; p < 4; p++) {
            const float pv = sPat[p][i];
            aq[p] = fmaf(pv, wq, aq[p]);
            ak[p] = fmaf(pv, wk, ak[p]);
            av[p] = fmaf(pv, wv, av[p]);
        }
    }
    #pragma unroll
    for (int o = 16; o; o >>= 1) {
        #pragma unroll
        for (int p = 0; p < 4; p++) {
            aq[p] += __shfl_xor_sync(0xffffffffu, aq[p], o);
            ak[p] += __shfl_xor_sync(0xffffffffu, ak[p], o);
            av[p] += __shfl_xor_sync(0xffffffffu, av[p], o);
        }
    }
    if (lane < 4) {
        const int p = lane;
        const int base = (b*NPATCH + n0 + p)*HID + w;
        g_q1[base] = aq[p] + bq[w];
        g_k1[base] = ak[p] + bk[w];
        g_v1[base] = av[p] + bv[w];
    }
}

// ---------------- attention stage 0: 4 queries/warp --------------------------
// grid (18, 6, 2), 256 threads. lane = (kg 0..7, qq 0..3). Keys interleaved.
__global__ void attn0_kernel() {
    const int b = blockIdx.z, s = blockIdx.y;
    const int tid = threadIdx.x;
    const int w = tid >> 5, lane = tid & 31;
    const int kg = lane >> 2, qq = lane & 3;
    const int qi = blockIdx.x*32 + w*4 + qq;

    const float4* q4 = (const float4*)(g_q1 + (b*NPATCH + qi)*HID);
    float4 qa = q4[0], qb = q4[1];
    qa.x *= SCALE; qa.y *= SCALE; qa.z *= SCALE; qa.w *= SCALE;
    qb.x *= SCALE; qb.y *= SCALE; qb.z *= SCALE; qb.w *= SCALE;

    float sum = 0.f;
    float4 A = {0,0,0,0}, B = {0,0,0,0};
    #pragma unroll
    for (int i = 0; i < 12; i++) {
        const int m = s*96 + i*8 + kg;
        const float4* k4 = (const float4*)(g_k1 + (b*NPATCH + m)*HID);
        float4 ka = k4[0], kb = k4[1];
        float d = qa.x*ka.x;
        d = fmaf(qa.y, ka.y, d); d = fmaf(qa.z, ka.z, d); d = fmaf(qa.w, ka.w, d);
        d = fmaf(qb.x, kb.x, d); d = fmaf(qb.y, kb.y, d);
        d = fmaf(qb.z, kb.z, d); d = fmaf(qb.w, kb.w, d);
        const float e = __expf(d);
        sum += e;
        const float4* v4 = (const float4*)(g_v1 + (b*NPATCH + m)*HID);
        float4 va = v4[0], vb = v4[1];
        A.x = fmaf(e, va.x, A.x); A.y = fmaf(e, va.y, A.y);
        A.z = fmaf(e, va.z, A.z); A.w = fmaf(e, va.w, A.w);
        B.x = fmaf(e, vb.x, B.x); B.y = fmaf(e, vb.y, B.y);
        B.z = fmaf(e, vb.z, B.z); B.w = fmaf(e, vb.w, B.w);
    }
    #pragma unroll
    for (int o = 16; o >= 4; o >>= 1) {     // reduce over kg bits only
        sum += __shfl_xor_sync(0xffffffffu, sum, o);
        A.x += __shfl_xor_sync(0xffffffffu, A.x, o);
        A.y += __shfl_xor_sync(0xffffffffu, A.y, o);
        A.z += __shfl_xor_sync(0xffffffffu, A.z, o);
        A.w += __shfl_xor_sync(0xffffffffu, A.w, o);
        B.x += __shfl_xor_sync(0xffffffffu, B.x, o);
        B.y += __shfl_xor_sync(0xffffffffu, B.y, o);
        B.z += __shfl_xor_sync(0xffffffffu, B.z, o);
        B.w += __shfl_xor_sync(0xffffffffu, B.w, o);
    }
    if (kg == 0) {
        float* p = g_part + ((b*SPLITS + s)*NPATCH + qi)*12;
        ((float4*)p)[0] = A;
        ((float4*)p)[1] = B;
        p[8] = sum;
    }
}

// ---------------- gather fo from stage-0 partials ----------------------------
__device__ __forceinline__ void gather_fo(const float* __restrict__ part,
                                          int b, int q, float fo[HID]) {
    float acc[HID];
    #pragma unroll
    for (int j = 0; j < HID; j++) acc[j] = 0.f;
    float sum = 0.f;
    #pragma unroll
    for (int s = 0; s < SPLITS; s++) {
        const float* p = part + ((b*SPLITS + s)*NPATCH + q)*12;
        float4 A = ((const float4*)p)[0];
        float4 B = ((const float4*)p)[1];
        acc[0]+=A.x; acc[1]+=A.y; acc[2]+=A.z; acc[3]+=A.w;
        acc[4]+=B.x; acc[5]+=B.y; acc[6]+=B.z; acc[7]+=B.w;
        sum += p[8];
    }
    const float inv = 1.f / sum;
    #pragma unroll
    for (int j = 0; j < HID; j++) fo[j] = acc[j]*inv;
}

// ---------------- stage 1 fused: fin1 (in-block) + attention ----------------
// grid (18, 6, 2), 256 threads. Prologue builds q2/k2/v2 rows in smem.
__global__ void attn1f_kernel(const float* __restrict__ Wsq, const float* __restrict__ bsq,
                              const float* __restrict__ Wsk, const float* __restrict__ bsk,
                              const float* __restrict__ Wsv, const float* __restrict__ bsv) {
    __shared__ __align__(16) float sQ[32*12];
    __shared__ __align__(16) float sK[96*12];
    __shared__ __align__(16) float sV[96*12];
    const int b = blockIdx.z, s = blockIdx.y;
    const int tid = threadIdx.x;

    // prologue: t<32 -> q2 (scaled); t in [32,128) -> k2; t in [128,224) -> v2
    if (tid < 224) {
        int patch, mode, slot;
        if (tid < 32)       { patch = blockIdx.x*32 + tid; mode = 0; slot = tid; }
        else if (tid < 128) { slot = tid - 32;  patch = s*96 + slot; mode = 1; }
        else                { slot = tid - 128; patch = s*96 + slot; mode = 2; }
        float fo[HID];
        gather_fo(g_part, b, patch, fo);
        const float* W = (mode == 0) ? Wsq : (mode == 1) ? Wsk : Wsv;
        const float* bb = (mode == 0) ? bsq : (mode == 1) ? bsk : bsv;
        float o[HID];
        #pragma unroll
        for (int j = 0; j < HID; j++) o[j] = bb[j];
        #pragma unroll
        for (int i = 0; i < HID; i++) {
            const float f = fo[i];
            #pragma unroll
            for (int j = 0; j < HID; j++) o[j] = fmaf(f, W[i*HID + j], o[j]);
        }
        float* dst = (mode == 0) ? (sQ + slot*12) : (mode == 1) ? (sK + slot*12) : (sV + slot*12);
        const float sc = (mode == 0) ? SCALE : 1.f;
        ((float4*)dst)[0] = make_float4(o[0]*sc, o[1]*sc, o[2]*sc, o[3]*sc);
        ((float4*)dst)[1] = make_float4(o[4]*sc, o[5]*sc, o[6]*sc, o[7]*sc);
    }
    __syncthreads();

    const int w = tid >> 5, lane = tid & 31;
    const int kg = lane >> 2, qq = lane & 3;
    const int qr = w*4 + qq;
    const float4* q4 = (const float4*)(sQ + qr*12);
    const float4 qa = q4[0], qb = q4[1];

    float sum = 0.f;
    float4 A = {0,0,0,0}, B = {0,0,0,0};
    #pragma unroll
    for (int i = 0; i < 12; i++) {
        const int kk = i*8 + kg;
        const float4* k4 = (const float4*)(sK + kk*12);
        float4 ka = k4[0], kb = k4[1];
        float d = qa.x*ka.x;
        d = fmaf(qa.y, ka.y, d); d = fmaf(qa.z, ka.z, d); d = fmaf(qa.w, ka.w, d);
        d = fmaf(qb.x, kb.x, d); d = fmaf(qb.y, kb.y, d);
        d = fmaf(qb.z, kb.z, d); d = fmaf(qb.w, kb.w, d);
        const float e = __expf(d);
        sum += e;
        const float4* v4 = (const float4*)(sV + kk*12);
        float4 va = v4[0], vb = v4[1];
        A.x = fmaf(e, va.x, A.x); A.y = fmaf(e, va.y, A.y);
        A.z = fmaf(e, va.z, A.z); A.w = fmaf(e, va.w, A.w);
        B.x = fmaf(e, vb.x, B.x); B.y = fmaf(e, vb.y, B.y);
        B.z = fmaf(e, vb.z, B.z); B.w = fmaf(e, vb.w, B.w);
    }
    #pragma unroll
    for (int o = 16; o >= 4; o >>= 1) {
        sum += __shfl_xor_sync(0xffffffffu, sum, o);
        A.x += __shfl_xor_sync(0xffffffffu, A.x, o);
        A.y += __shfl_xor_sync(0xffffffffu, A.y, o);
        A.z += __shfl_xor_sync(0xffffffffu, A.z, o);
        A.w += __shfl_xor_sync(0xffffffffu, A.w, o);
        B.x += __shfl_xor_sync(0xffffffffu, B.x, o);
        B.y += __shfl_xor_sync(0xffffffffu, B.y, o);
        B.z += __shfl_xor_sync(0xffffffffu, B.z, o);
        B.w += __shfl_xor_sync(0xffffffffu, B.w, o);
    }
    if (kg == 0) {
        const int qi = blockIdx.x*32 + qr;
        float* p = g_part2 + ((b*SPLITS + s)*NPATCH + qi)*12;
        ((float4*)p)[0] = A;
        ((float4*)p)[1] = B;
        p[8] = sum;
    }
}

// ---------------- fin2: layernorm + sigma head + global max -----------------
__global__ void fin2_kernel(const float* __restrict__ ln_g, const float* __restrict__ ln_b,
                            const float* __restrict__ Wp,   const float* __restrict__ bp) {
    const int t = blockIdx.x*256 + threadIdx.x;
    if (t >= NB*NPATCH) return;
    const int b = t / NPATCH, q = t % NPATCH;
    float fo[HID];
    gather_fo(g_part2, b, q, fo);
    float mu = 0.f;
    #pragma unroll
    for (int j = 0; j < HID; j++) mu += fo[j];
    mu *= 0.125f;
    float var = 0.f;
    #pragma unroll
    for (int j = 0; j < HID; j++) { float d = fo[j]-mu; var = fmaf(d,d,var); }
    var *= 0.125f;
    const float rstd = rsqrtf(var + 1e-5f);
    float oin[HID];
    #pragma unroll
    for (int j = 0; j < HID; j++) oin[j] = (fo[j]-mu)*rstd*ln_g[j] + ln_b[j];
    float sig[3];
    #pragma unroll
    for (int j = 0; j < 3; j++) {
        float sv = bp[j];
        #pragma unroll
        for (int i = 0; i < HID; i++) sv = fmaf(oin[i], Wp[i*3 + j], sv);
        float spv = (sv > 20.f) ? sv : log1pf(expf(sv));
        sig[j] = fminf(spv, 6.0f) + 1e-6f;
        g_s[(b*NPATCH + q)*3 + j] = sig[j];
    }
    const float mx = fmaxf(sig[0], sig[1]);
    atomicMax(&g_max, __float_as_int(mx));   // positive floats: int order ok
}

// ---------------- bilateral core (templated, f32x2 packed) -------------------
template<int K>
__device__ __forceinline__ float bilat_core(const float* tb, const float* spP,
                                            int r, float c, u64 C1, u64 C2, u64 C3) {
    constexpr int KE = K + 1, KE2 = KE/2;
    const u64 c2   = pk2(c, c);
    const u64 NEG1 = pk2(-1.f, -1.f);
    const u64 ONE2 = pk2(1.f, 1.f);
    u64 ws = 0ull, ac = 0ull;        // bit pattern of (0.f, 0.f)
    #pragma unroll
    for (int dy = 0; dy < K; dy++) {
        const u64* trow = (const u64*)(tb + (r + dy)*32);
        const u64* srow = (const u64*)(spP + dy*KE);
        #pragma unroll
        for (int j = 0; j < KE2; j++) {
            u64 p2 = trow[j];
            u64 s2 = srow[j];
            u64 d2 = fma2_(p2, NEG1, c2);        // c - p
            u64 dd = mul2_(d2, d2);
            u64 t2 = fma2_(dd, C3, C2);
            t2     = fma2_(dd, t2, C1);
            u64 rg = fma2_(dd, t2, ONE2);        // ~exp(dd*ir), 3rd-order
            u64 w2 = mul2_(s2, rg);
            ws     = add2_(ws, w2);
            ac     = fma2_(w2, p2, ac);
        }
    }
    float2 w = upk2(ws), a = upk2(ac);
    return (a.x + a.y) / ((w.x + w.y) + 1e-8f);
}

// ---------------- bilateral filter ------------------------------------------
__global__ void bilateral_kernel(const float* __restrict__ x, float* __restrict__ out) {
    __shared__ __align__(16) float tE[1056];   // tile, stride 32
    __shared__ __align__(16) float tO[1056];   // tO[i] = tile[i+1]
    __shared__ __align__(16) float spP[324];   // spatial table, stride kE (even)
    const int n = blockIdx.x, b = blockIdx.y;
    const int hp = n / GRIDP, wn = n % GRIDP;
    const int tid = threadIdx.x;

    const float m = __int_as_float(g_max);
    const int half = (int)ceilf(m + 1.0f);
    const int k = 2*half + 1, kE = k + 1;

    const float* sv = g_s + (b*NPATCH + n)*3;
    const float sx = sv[0], sy = sv[1], sr = sv[2];
    const float ix = -0.5f/(sx*sx), iy = -0.5f/(sy*sy), ir = -0.5f/(sr*sr);
    const float c1 = ir, c2c = 0.5f*ir*ir, c3c = ir*ir*ir*(1.f/6.f);
    const u64 C1 = pk2(c1,c1), C2 = pk2(c2c,c2c), C3 = pk2(c3c,c3c);

    const int y0 = hp*PS - half, x0 = wn*PS - half;
    const float* xb = x + b*HW*HW;
    for (int i = tid; i < 1056; i += 256) {
        int ty = i >> 5, tx = i & 31;
        int gy = y0 + ty, gx = x0 + tx;
        float v = 0.f;
        if ((unsigned)gy < HW && (unsigned)gx < HW) v = xb[gy*HW + gx];
        tE[i] = v;
        if (i > 0) tO[i-1] = v;
    }
    const int kkE = k*kE;
    for (int t = tid; t < kkE; t += 256) {
        int dy = t / kE, dx = t - dy*kE;
        float val = 0.f;
        if (dx < k) {
            float fx = (float)(dx - half), fy = (float)(dy - half);
            val = __expf(fx*fx*ix + fy*fy*iy);
        }
        spP[t] = val;
    }
    __syncthreads();

    const int r = tid >> 4, cc = tid & 15;
    const float* tb = (cc & 1) ? (tO + cc - 1) : (tE + cc);
    const float c = tE[(r + half)*32 + cc + half];

    float res;
    switch (k) {
        case 3:  res = bilat_core<3 >(tb, spP, r, c, C1, C2, C3); break;
        case 5:  res = bilat_core<5 >(tb, spP, r, c, C1, C2, C3); break;
        case 7:  res = bilat_core<7 >(tb, spP, r, c, C1, C2, C3); break;
        case 9:  res = bilat_core<9 >(tb, spP, r, c, C1, C2, C3); break;
        case 11: res = bilat_core<11>(tb, spP, r, c, C1, C2, C3); break;
        case 13: res = bilat_core<13>(tb, spP, r, c, C1, C2, C3); break;
        case 15: res = bilat_core<15>(tb, spP, r, c, C1, C2, C3); break;
        case 17: res = bilat_core<17>(tb, spP, r, c, C1, C2, C3); break;
        default: {   // generic fallback (never expected)
            float acc = 0.f, wsum = 0.f;
            for (int dy = 0; dy < k; dy++) {
                const float* trow = tE + (r + dy)*32 + cc;
                const float* srow = spP + dy*kE;
                for (int dx = 0; dx < k; dx++) {
                    float p = trow[dx];
                    float d = c - p;
                    float w = srow[dx] * __expf(d*d*ir);
                    wsum += w;
                    acc = fmaf(w, p, acc);
                }
            }
            res = acc / (wsum + 1e-8f);
        }
    }
    out[(b*HW + hp*PS + r)*HW + wn*PS + cc] = res;
}

// ---------------- launcher ---------------------------------------------------
extern "C" void kernel_launch(void* const* d_in, const int* in_sizes, int n_in,
                              void* d_out, int out_size) {
    const float* x    = (const float*)d_in[0];
    const float* Wq   = (const float*)d_in[1];
    const float* bq   = (const float*)d_in[2];
    const float* Wk   = (const float*)d_in[3];
    const float* bk   = (const float*)d_in[4];
    const float* Wv   = (const float*)d_in[5];
    const float* bv   = (const float*)d_in[6];
    const float* Wsq  = (const float*)d_in[7];
    const float* bsq  = (const float*)d_in[8];
    const float* Wsk  = (const float*)d_in[9];
    const float* bsk  = (const float*)d_in[10];
    const float* Wsv  = (const float*)d_in[11];
    const float* bsv  = (const float*)d_in[12];
    const float* ln_g = (const float*)d_in[13];
    const float* ln_b = (const float*)d_in[14];
    const float* Wp   = (const float*)d_in[15];
    const float* bp   = (const float*)d_in[16];
    float* out = (float*)d_out;

    qkv_kernel<<<dim3(NPATCH/4, NB), 256>>>(x, Wq, bq, Wk, bk, Wv, bv);
    attn0_kernel<<<dim3(NPATCH/32, SPLITS, NB), 256>>>();
    attn1f_kernel<<<dim3(NPATCH/32, SPLITS, NB), 256>>>(Wsq, bsq, Wsk, bsk, Wsv, bsv);
    fin2_kernel<<<(NB*NPATCH + 255)/256, 256>>>(ln_g, ln_b, Wp, bp);
    bilateral_kernel<<<dim3(NPATCH, NB), 256>>>(x, out);
}

// round 6
// speedup vs baseline: 1.6104x; 1.0514x over previous
#include <cuda_runtime.h>
#include <math.h>

#define PS    16
#define HID   8
#define GRIDP 24
#define NPATCH 576      // 24*24
#define NB    2
#define HW    384
#define DIN   256
#define SCALE 0.35355339059327373f

typedef unsigned long long u64;

// ---------------- scratch (device globals; no allocation allowed) ----------
__device__ float g_q1[NB*NPATCH*HID];
__device__ float g_k1[NB*NPATCH*HID];
__device__ float g_v1[NB*NPATCH*HID];
__device__ float g_fo[NB*NPATCH*HID];    // normalized stage-0 attention output
__device__ float g_s [NB*NPATCH*3];
__device__ int   g_max;

// ---------------- packed f32x2 helpers (Blackwell) --------------------------
__device__ __forceinline__ u64 pk2(float lo, float hi){
    u64 r; asm("mov.b64 %0, {%1, %2};" : "=l"(r) : "f"(lo), "f"(hi)); return r;
}
__device__ __forceinline__ float2 upk2(u64 v){
    float2 f; asm("mov.b64 {%0, %1}, %2;" : "=f"(f.x), "=f"(f.y) : "l"(v)); return f;
}
__device__ __forceinline__ u64 fma2_(u64 a, u64 b, u64 c){
    u64 d; asm("fma.rn.f32x2 %0, %1, %2, %3;" : "=l"(d) : "l"(a), "l"(b), "l"(c)); return d;
}
__device__ __forceinline__ u64 mul2_(u64 a, u64 b){
    u64 d; asm("mul.rn.f32x2 %0, %1, %2;" : "=l"(d) : "l"(a), "l"(b)); return d;
}
__device__ __forceinline__ u64 add2_(u64 a, u64 b){
    u64 d; asm("add.rn.f32x2 %0, %1, %2;" : "=l"(d) : "l"(a), "l"(b)); return d;
}

// ---------------- qkv: 4 patches/block, smem-staged transposed W ------------
__global__ void qkv_kernel(const float* __restrict__ x,
                           const float* __restrict__ Wq, const float* __restrict__ bq,
                           const float* __restrict__ Wk, const float* __restrict__ bk,
                           const float* __restrict__ Wv, const float* __restrict__ bv) {
    __shared__ float sWq[DIN*9], sWk[DIN*9], sWv[DIN*9];   // [i*9 + col], pad 9
    __shared__ float sPat[4][DIN];
    const int n0 = blockIdx.x * 4, b = blockIdx.y;
    const int tid = threadIdx.x;
    if (blockIdx.x == 0 && b == 0 && tid == 0) g_max = 0;  // fold init

    #pragma unroll
    for (int e = tid; e < DIN*HID; e += 256) {
        int idx = (e >> 3)*9 + (e & 7);
        sWq[idx] = Wq[e]; sWk[idx] = Wk[e]; sWv[idx] = Wv[e];
    }
    const int r = tid >> 4, cc = tid & 15;
    #pragma unroll
    for (int p = 0; p < 4; p++) {
        int n = n0 + p;
        int hp = n / GRIDP, wn = n % GRIDP;
        sPat[p][tid] = x[(b*HW + hp*PS + r)*HW + wn*PS + cc];
    }
    __syncthreads();

    const int w = tid >> 5, lane = tid & 31;
    float aq[4] = {0,0,0,0}, ak[4] = {0,0,0,0}, av[4] = {0,0,0,0};
    #pragma unroll
    for (int it = 0; it < DIN/32; ++it) {
        const int i = lane + 32*it;
        const float wq = sWq[i*9 + w], wk = sWk[i*9 + w], wv = sWv[i*9 + w];
        #pragma unroll
        for (int p = 0; p < 4; p++) {
            const float pv = sPat[p][i];
            aq[p] = fmaf(pv, wq, aq[p]);
            ak[p] = fmaf(pv, wk, ak[p]);
            av[p] = fmaf(pv, wv, av[p]);
        }
    }
    #pragma unroll
    for (int o = 16; o; o >>= 1) {
        #pragma unroll
        for (int p = 0; p < 4; p++) {
            aq[p] += __shfl_xor_sync(0xffffffffu, aq[p], o);
            ak[p] += __shfl_xor_sync(0xffffffffu, ak[p], o);
            av[p] += __shfl_xor_sync(0xffffffffu, av[p], o);
        }
    }
    if (lane < 4) {
        const int p = lane;
        const int base = (b*NPATCH + n0 + p)*HID + w;
        g_q1[base] = aq[p] + bq[w];
        g_k1[base] = ak[p] + bk[w];
        g_v1[base] = av[p] + bv[w];
    }
}

// ---------------- attention stage 0: full keys in smem, 4 queries/warp ------
// grid (18, 2), 256 threads. lane = (kg 0..7, qq 0..3). Writes normalized fo.
__global__ void attn0_kernel() {
    __shared__ __align__(16) float sK[NPATCH*8];
    __shared__ __align__(16) float sV[NPATCH*8];
    const int b = blockIdx.y;
    const int tid = threadIdx.x;

    const float4* k4g = (const float4*)(g_k1 + b*NPATCH*HID);
    const float4* v4g = (const float4*)(g_v1 + b*NPATCH*HID);
    #pragma unroll
    for (int t = tid; t < NPATCH*2; t += 256) {
        ((float4*)sK)[t] = k4g[t];
        ((float4*)sV)[t] = v4g[t];
    }
    __syncthreads();

    const int w = tid >> 5, lane = tid & 31;
    const int kg = lane >> 2, qq = lane & 3;
    const int qi = blockIdx.x*32 + w*4 + qq;

    const float4* q4 = (const float4*)(g_q1 + (b*NPATCH + qi)*HID);
    float4 qa = q4[0], qb = q4[1];
    qa.x *= SCALE; qa.y *= SCALE; qa.z *= SCALE; qa.w *= SCALE;
    qb.x *= SCALE; qb.y *= SCALE; qb.z *= SCALE; qb.w *= SCALE;

    float sum = 0.f;
    float4 A = {0,0,0,0}, B = {0,0,0,0};
    #pragma unroll 8
    for (int i = 0; i < NPATCH/8; i++) {
        const int m = i*8 + kg;
        const float4* k4 = (const float4*)(sK + m*8);
        float4 ka = k4[0], kb = k4[1];
        float d = qa.x*ka.x;
        d = fmaf(qa.y, ka.y, d); d = fmaf(qa.z, ka.z, d); d = fmaf(qa.w, ka.w, d);
        d = fmaf(qb.x, kb.x, d); d = fmaf(qb.y, kb.y, d);
        d = fmaf(qb.z, kb.z, d); d = fmaf(qb.w, kb.w, d);
        const float e = __expf(d);
        sum += e;
        const float4* v4 = (const float4*)(sV + m*8);
        float4 va = v4[0], vb = v4[1];
        A.x = fmaf(e, va.x, A.x); A.y = fmaf(e, va.y, A.y);
        A.z = fmaf(e, va.z, A.z); A.w = fmaf(e, va.w, A.w);
        B.x = fmaf(e, vb.x, B.x); B.y = fmaf(e, vb.y, B.y);
        B.z = fmaf(e, vb.z, B.z); B.w = fmaf(e, vb.w, B.w);
    }
    #pragma unroll
    for (int o = 16; o >= 4; o >>= 1) {     // reduce over kg bits only
        sum += __shfl_xor_sync(0xffffffffu, sum, o);
        A.x += __shfl_xor_sync(0xffffffffu, A.x, o);
        A.y += __shfl_xor_sync(0xffffffffu, A.y, o);
        A.z += __shfl_xor_sync(0xffffffffu, A.z, o);
        A.w += __shfl_xor_sync(0xffffffffu, A.w, o);
        B.x += __shfl_xor_sync(0xffffffffu, B.x, o);
        B.y += __shfl_xor_sync(0xffffffffu, B.y, o);
        B.z += __shfl_xor_sync(0xffffffffu, B.z, o);
        B.w += __shfl_xor_sync(0xffffffffu, B.w, o);
    }
    if (kg == 0) {
        const float inv = 1.f / sum;
        float4* dst = (float4*)(g_fo + (b*NPATCH + qi)*HID);
        dst[0] = make_float4(A.x*inv, A.y*inv, A.z*inv, A.w*inv);
        dst[1] = make_float4(B.x*inv, B.y*inv, B.z*inv, B.w*inv);
    }
}

// ---------------- stage 1 fused: projections + attention + LN + sigma head --
// grid (18, 2), 256 threads.
__global__ void attn1_kernel(const float* __restrict__ Wsq, const float* __restrict__ bsq,
                             const float* __restrict__ Wsk, const float* __restrict__ bsk,
                             const float* __restrict__ Wsv, const float* __restrict__ bsv,
                             const float* __restrict__ ln_g, const float* __restrict__ ln_b,
                             const float* __restrict__ Wp,   const float* __restrict__ bp) {
    __shared__ float sW[3][72];                 // 64 weights + 8 bias each
    __shared__ __align__(16) float sQ[32*8];
    __shared__ __align__(16) float sK[NPATCH*8];
    __shared__ __align__(16) float sV[NPATCH*8];
    const int b = blockIdx.y;
    const int tid = threadIdx.x;

    if (tid < 64) {
        sW[0][tid] = Wsq[tid]; sW[1][tid] = Wsk[tid]; sW[2][tid] = Wsv[tid];
    } else if (tid < 72) {
        int j = tid - 64;
        sW[0][64+j] = bsq[j]; sW[1][64+j] = bsk[j]; sW[2][64+j] = bsv[j];
    }
    __syncthreads();

    // prologue: project fo -> q2 (32 rows, scaled) / k2 (576) / v2 (576)
    for (int t = tid; t < 32 + 2*NPATCH; t += 256) {
        int mode, slot, patch;
        if (t < 32)              { mode = 0; slot = t;             patch = blockIdx.x*32 + t; }
        else if (t < 32+NPATCH)  { mode = 1; slot = t - 32;        patch = slot; }
        else                     { mode = 2; slot = t - 32-NPATCH; patch = slot; }
        const float4* f4 = (const float4*)(g_fo + (b*NPATCH + patch)*HID);
        const float4 fa = f4[0], fb = f4[1];
        const float fo[HID] = {fa.x, fa.y, fa.z, fa.w, fb.x, fb.y, fb.z, fb.w};
        const float* W = sW[mode];
        float o[HID];
        #pragma unroll
        for (int j = 0; j < HID; j++) o[j] = W[64 + j];
        #pragma unroll
        for (int i = 0; i < HID; i++) {
            const float f = fo[i];
            #pragma unroll
            for (int j = 0; j < HID; j++) o[j] = fmaf(f, W[i*HID + j], o[j]);
        }
        const float sc = (mode == 0) ? SCALE : 1.f;
        float* dst = (mode == 0) ? (sQ + slot*8) : (mode == 1) ? (sK + slot*8) : (sV + slot*8);
        ((float4*)dst)[0] = make_float4(o[0]*sc, o[1]*sc, o[2]*sc, o[3]*sc);
        ((float4*)dst)[1] = make_float4(o[4]*sc, o[5]*sc, o[6]*sc, o[7]*sc);
    }
    __syncthreads();

    const int w = tid >> 5, lane = tid & 31;
    const int kg = lane >> 2, qq = lane & 3;
    const int qr = w*4 + qq;

    const float4* q4 = (const float4*)(sQ + qr*8);
    const float4 qa = q4[0], qb = q4[1];

    float sum = 0.f;
    float4 A = {0,0,0,0}, B = {0,0,0,0};
    #pragma unroll 8
    for (int i = 0; i < NPATCH/8; i++) {
        const int m = i*8 + kg;
        const float4* k4 = (const float4*)(sK + m*8);
        float4 ka = k4[0], kb = k4[1];
        float d = qa.x*ka.x;
        d = fmaf(qa.y, ka.y, d); d = fmaf(qa.z, ka.z, d); d = fmaf(qa.w, ka.w, d);
        d = fmaf(qb.x, kb.x, d); d = fmaf(qb.y, kb.y, d);
        d = fmaf(qb.z, kb.z, d); d = fmaf(qb.w, kb.w, d);
        const float e = __expf(d);
        sum += e;
        const float4* v4 = (const float4*)(sV + m*8);
        float4 va = v4[0], vb = v4[1];
        A.x = fmaf(e, va.x, A.x); A.y = fmaf(e, va.y, A.y);
        A.z = fmaf(e, va.z, A.z); A.w = fmaf(e, va.w, A.w);
        B.x = fmaf(e, vb.x, B.x); B.y = fmaf(e, vb.y, B.y);
        B.z = fmaf(e, vb.z, B.z); B.w = fmaf(e, vb.w, B.w);
    }
    #pragma unroll
    for (int o = 16; o >= 4; o >>= 1) {
        sum += __shfl_xor_sync(0xffffffffu, sum, o);
        A.x += __shfl_xor_sync(0xffffffffu, A.x, o);
        A.y += __shfl_xor_sync(0xffffffffu, A.y, o);
        A.z += __shfl_xor_sync(0xffffffffu, A.z, o);
        A.w += __shfl_xor_sync(0xffffffffu, A.w, o);
        B.x += __shfl_xor_sync(0xffffffffu, B.x, o);
        B.y += __shfl_xor_sync(0xffffffffu, B.y, o);
        B.z += __shfl_xor_sync(0xffffffffu, B.z, o);
        B.w += __shfl_xor_sync(0xffffffffu, B.w, o);
    }
    if (kg == 0) {
        const float inv = 1.f / sum;
        float fo[HID] = {A.x*inv, A.y*inv, A.z*inv, A.w*inv,
                         B.x*inv, B.y*inv, B.z*inv, B.w*inv};
        float mu = 0.f;
        #pragma unroll
        for (int j = 0; j < HID; j++) mu += fo[j];
        mu *= 0.125f;
        float var = 0.f;
        #pragma unroll
        for (int j = 0; j < HID; j++) { float d = fo[j]-mu; var = fmaf(d,d,var); }
        var *= 0.125f;
        const float rstd = rsqrtf(var + 1e-5f);
        float oin[HID];
        #pragma unroll
        for (int j = 0; j < HID; j++) oin[j] = (fo[j]-mu)*rstd*ln_g[j] + ln_b[j];
        const int qi = blockIdx.x*32 + qr;
        float sig[3];
        #pragma unroll
        for (int j = 0; j < 3; j++) {
            float sv = bp[j];
            #pragma unroll
            for (int i = 0; i < HID; i++) sv = fmaf(oin[i], Wp[i*3 + j], sv);
            float spv = (sv > 20.f) ? sv : log1pf(expf(sv));
            sig[j] = fminf(spv, 6.0f) + 1e-6f;
            g_s[(b*NPATCH + qi)*3 + j] = sig[j];
        }
        const float mx = fmaxf(sig[0], sig[1]);
        atomicMax(&g_max, __float_as_int(mx));   // positive floats: int order ok
    }
}

// ---------------- bilateral core (templated, f32x2 packed) -------------------
template<int K>
__device__ __forceinline__ float bilat_core(const float* tb, const float* spP,
                                            int r, float c, u64 C1, u64 C2, u64 C3) {
    constexpr int KE = K + 1, KE2 = KE/2;
    const u64 c2   = pk2(c, c);
    const u64 NEG1 = pk2(-1.f, -1.f);
    const u64 ONE2 = pk2(1.f, 1.f);
    u64 ws = 0ull, ac = 0ull;        // bit pattern of (0.f, 0.f)
    #pragma unroll
    for (int dy = 0; dy < K; dy++) {
        const u64* trow = (const u64*)(tb + (r + dy)*32);
        const u64* srow = (const u64*)(spP + dy*KE);
        #pragma unroll
        for (int j = 0; j < KE2; j++) {
            u64 p2 = trow[j];
            u64 s2 = srow[j];
            u64 d2 = fma2_(p2, NEG1, c2);        // c - p
            u64 dd = mul2_(d2, d2);
            u64 t2 = fma2_(dd, C3, C2);
            t2     = fma2_(dd, t2, C1);
            u64 rg = fma2_(dd, t2, ONE2);        // ~exp(dd*ir), 3rd-order
            u64 w2 = mul2_(s2, rg);
            ws     = add2_(ws, w2);
            ac     = fma2_(w2, p2, ac);
        }
    }
    float2 w = upk2(ws), a = upk2(ac);
    return (a.x + a.y) / ((w.x + w.y) + 1e-8f);
}

// ---------------- bilateral filter ------------------------------------------
__global__ void bilateral_kernel(const float* __restrict__ x, float* __restrict__ out) {
    __shared__ __align__(16) float tE[1056];   // tile, stride 32
    __shared__ __align__(16) float tO[1056];   // tO[i] = tile[i+1]
    __shared__ __align__(16) float spP[324];   // spatial table, stride kE (even)
    const int n = blockIdx.x, b = blockIdx.y;
    const int hp = n / GRIDP, wn = n % GRIDP;
    const int tid = threadIdx.x;

    const float m = __int_as_float(g_max);
    const int half = (int)ceilf(m + 1.0f);
    const int k = 2*half + 1, kE = k + 1;

    const float* sv = g_s + (b*NPATCH + n)*3;
    const float sx = sv[0], sy = sv[1], sr = sv[2];
    const float ix = -0.5f/(sx*sx), iy = -0.5f/(sy*sy), ir = -0.5f/(sr*sr);
    const float c1 = ir, c2c = 0.5f*ir*ir, c3c = ir*ir*ir*(1.f/6.f);
    const u64 C1 = pk2(c1,c1), C2 = pk2(c2c,c2c), C3 = pk2(c3c,c3c);

    const int y0 = hp*PS - half, x0 = wn*PS - half;
    const float* xb = x + b*HW*HW;
    for (int i = tid; i < 1056; i += 256) {
        int ty = i >> 5, tx = i & 31;
        int gy = y0 + ty, gx = x0 + tx;
        float v = 0.f;
        if ((unsigned)gy < HW && (unsigned)gx < HW) v = xb[gy*HW + gx];
        tE[i] = v;
        if (i > 0) tO[i-1] = v;
    }
    const int kkE = k*kE;
    for (int t = tid; t < kkE; t += 256) {
        int dy = t / kE, dx = t - dy*kE;
        float val = 0.f;
        if (dx < k) {
            float fx = (float)(dx - half), fy = (float)(dy - half);
            val = __expf(fx*fx*ix + fy*fy*iy);
        }
        spP[t] = val;
    }
    __syncthreads();

    const int r = tid >> 4, cc = tid & 15;
    const float* tb = (cc & 1) ? (tO + cc - 1) : (tE + cc);
    const float c = tE[(r + half)*32 + cc + half];

    float res;
    switch (k) {
        case 3:  res = bilat_core<3 >(tb, spP, r, c, C1, C2, C3); break;
        case 5:  res = bilat_core<5 >(tb, spP, r, c, C1, C2, C3); break;
        case 7:  res = bilat_core<7 >(tb, spP, r, c, C1, C2, C3); break;
        case 9:  res = bilat_core<9 >(tb, spP, r, c, C1, C2, C3); break;
        case 11: res = bilat_core<11>(tb, spP, r, c, C1, C2, C3); break;
        case 13: res = bilat_core<13>(tb, spP, r, c, C1, C2, C3); break;
        case 15: res = bilat_core<15>(tb, spP, r, c, C1, C2, C3); break;
        case 17: res = bilat_core<17>(tb, spP, r, c, C1, C2, C3); break;
        default: {   // generic fallback (never expected)
            float acc = 0.f, wsum = 0.f;
            for (int dy = 0; dy < k; dy++) {
                const float* trow = tE + (r + dy)*32 + cc;
                const float* srow = spP + dy*kE;
                for (int dx = 0; dx < k; dx++) {
                    float p = trow[dx];
                    float d = c - p;
                    float w = srow[dx] * __expf(d*d*ir);
                    wsum += w;
                    acc = fmaf(w, p, acc);
                }
            }
            res = acc / (wsum + 1e-8f);
        }
    }
    out[(b*HW + hp*PS + r)*HW + wn*PS + cc] = res;
}

// ---------------- launcher ---------------------------------------------------
extern "C" void kernel_launch(void* const* d_in, const int* in_sizes, int n_in,
                              void* d_out, int out_size) {
    const float* x    = (const float*)d_in[0];
    const float* Wq   = (const float*)d_in[1];
    const float* bq   = (const float*)d_in[2];
    const float* Wk   = (const float*)d_in[3];
    const float* bk   = (const float*)d_in[4];
    const float* Wv   = (const float*)d_in[5];
    const float* bv   = (const float*)d_in[6];
    const float* Wsq  = (const float*)d_in[7];
    const float* bsq  = (const float*)d_in[8];
    const float* Wsk  = (const float*)d_in[9];
    const float* bsk  = (const float*)d_in[10];
    const float* Wsv  = (const float*)d_in[11];
    const float* bsv  = (const float*)d_in[12];
    const float* ln_g = (const float*)d_in[13];
    const float* ln_b = (const float*)d_in[14];
    const float* Wp   = (const float*)d_in[15];
    const float* bp   = (const float*)d_in[16];
    float* out = (float*)d_out;

    qkv_kernel<<<dim3(NPATCH/4, NB), 256>>>(x, Wq, bq, Wk, bk, Wv, bv);
    attn0_kernel<<<dim3(NPATCH/32, NB), 256>>>();
    attn1_kernel<<<dim3(NPATCH/32, NB), 256>>>(Wsq, bsq, Wsk, bsk, Wsv, bsv,
                                               ln_g, ln_b, Wp, bp);
    bilateral_kernel<<<dim3(NPATCH, NB), 256>>>(x, out);
}

// round 7
// speedup vs baseline: 1.9821x; 1.2308x over previous
#include <cuda_runtime.h>
#include <math.h>

#define PS    16
#define HID   8
#define GRIDP 24
#define NPATCH 576      // 24*24
#define NB    2
#define HW    384
#define DIN   256
#define SCALE 0.35355339059327373f

#define TSTR  48        // tile row stride (floats): 48 % 32 banks == 16 -> half-warp clean
#define MSTR  45        // moment row stride (u64)

typedef unsigned long long u64;

// ---------------- scratch (device globals; no allocation allowed) ----------
__device__ float g_q1[NB*NPATCH*HID];
__device__ float g_k1[NB*NPATCH*HID];
__device__ float g_v1[NB*NPATCH*HID];
__device__ float g_fo[NB*NPATCH*HID];    // normalized stage-0 attention output
__device__ float g_s [NB*NPATCH*3];
__device__ int   g_max;

// ---------------- packed f32x2 helpers (Blackwell) --------------------------
__device__ __forceinline__ u64 pk2(float lo, float hi){
    u64 r; asm("mov.b64 %0, {%1, %2};" : "=l"(r) : "f"(lo), "f"(hi)); return r;
}
__device__ __forceinline__ float2 upk2(u64 v){
    float2 f; asm("mov.b64 {%0, %1}, %2;" : "=f"(f.x), "=f"(f.y) : "l"(v)); return f;
}
__device__ __forceinline__ u64 fma2_(u64 a, u64 b, u64 c){
    u64 d; asm("fma.rn.f32x2 %0, %1, %2, %3;" : "=l"(d) : "l"(a), "l"(b), "l"(c)); return d;
}
__device__ __forceinline__ u64 mul2_(u64 a, u64 b){
    u64 d; asm("mul.rn.f32x2 %0, %1, %2;" : "=l"(d) : "l"(a), "l"(b)); return d;
}
__device__ __forceinline__ u64 add2_(u64 a, u64 b){
    u64 d; asm("add.rn.f32x2 %0, %1, %2;" : "=l"(d) : "l"(a), "l"(b)); return d;
}

// ---------------- qkv: 4 patches/block, smem-staged transposed W ------------
__global__ void qkv_kernel(const float* __restrict__ x,
                           const float* __restrict__ Wq, const float* __restrict__ bq,
                           const float* __restrict__ Wk, const float* __restrict__ bk,
                           const float* __restrict__ Wv, const float* __restrict__ bv) {
    __shared__ float sWq[DIN*9], sWk[DIN*9], sWv[DIN*9];   // [i*9 + col], pad 9
    __shared__ float sPat[4][DIN];
    const int n0 = blockIdx.x * 4, b = blockIdx.y;
    const int tid = threadIdx.x;
    if (blockIdx.x == 0 && b == 0 && tid == 0) g_max = 0;  // fold init

    #pragma unroll
    for (int e = tid; e < DIN*HID; e += 256) {
        int idx = (e >> 3)*9 + (e & 7);
        sWq[idx] = Wq[e]; sWk[idx] = Wk[e]; sWv[idx] = Wv[e];
    }
    const int r = tid >> 4, cc = tid & 15;
    #pragma unroll
    for (int p = 0; p < 4; p++) {
        int n = n0 + p;
        int hp = n / GRIDP, wn = n % GRIDP;
        sPat[p][tid] = x[(b*HW + hp*PS + r)*HW + wn*PS + cc];
    }
    __syncthreads();

    const int w = tid >> 5, lane = tid & 31;
    float aq[4] = {0,0,0,0}, ak[4] = {0,0,0,0}, av[4] = {0,0,0,0};
    #pragma unroll
    for (int it = 0; it < DIN/32; ++it) {
        const int i = lane + 32*it;
        const float wq = sWq[i*9 + w], wk = sWk[i*9 + w], wv = sWv[i*9 + w];
        #pragma unroll
        for (int p = 0; p < 4; p++) {
            const float pv = sPat[p][i];
            aq[p] = fmaf(pv, wq, aq[p]);
            ak[p] = fmaf(pv, wk, ak[p]);
            av[p] = fmaf(pv, wv, av[p]);
        }
    }
    #pragma unroll
    for (int o = 16; o; o >>= 1) {
        #pragma unroll
        for (int p = 0; p < 4; p++) {
            aq[p] += __shfl_xor_sync(0xffffffffu, aq[p], o);
            ak[p] += __shfl_xor_sync(0xffffffffu, ak[p], o);
            av[p] += __shfl_xor_sync(0xffffffffu, av[p], o);
        }
    }
    if (lane < 4) {
        const int p = lane;
        const int base = (b*NPATCH + n0 + p)*HID + w;
        g_q1[base] = aq[p] + bq[w];
        g_k1[base] = ak[p] + bk[w];
        g_v1[base] = av[p] + bv[w];
    }
}

// ---------------- attention stage 0: full keys in smem, 4 queries/warp ------
__global__ void attn0_kernel() {
    __shared__ __align__(16) float sK[NPATCH*8];
    __shared__ __align__(16) float sV[NPATCH*8];
    const int b = blockIdx.y;
    const int tid = threadIdx.x;

    const float4* k4g = (const float4*)(g_k1 + b*NPATCH*HID);
    const float4* v4g = (const float4*)(g_v1 + b*NPATCH*HID);
    #pragma unroll
    for (int t = tid; t < NPATCH*2; t += 256) {
        ((float4*)sK)[t] = k4g[t];
        ((float4*)sV)[t] = v4g[t];
    }
    __syncthreads();

    const int w = tid >> 5, lane = tid & 31;
    const int kg = lane >> 2, qq = lane & 3;
    const int qi = blockIdx.x*32 + w*4 + qq;

    const float4* q4 = (const float4*)(g_q1 + (b*NPATCH + qi)*HID);
    float4 qa = q4[0], qb = q4[1];
    qa.x *= SCALE; qa.y *= SCALE; qa.z *= SCALE; qa.w *= SCALE;
    qb.x *= SCALE; qb.y *= SCALE; qb.z *= SCALE; qb.w *= SCALE;

    float sum = 0.f;
    float4 A = {0,0,0,0}, B = {0,0,0,0};
    #pragma unroll 8
    for (int i = 0; i < NPATCH/8; i++) {
        const int m = i*8 + kg;
        const float4* k4 = (const float4*)(sK + m*8);
        float4 ka = k4[0], kb = k4[1];
        float d = qa.x*ka.x;
        d = fmaf(qa.y, ka.y, d); d = fmaf(qa.z, ka.z, d); d = fmaf(qa.w, ka.w, d);
        d = fmaf(qb.x, kb.x, d); d = fmaf(qb.y, kb.y, d);
        d = fmaf(qb.z, kb.z, d); d = fmaf(qb.w, kb.w, d);
        const float e = __expf(d);
        sum += e;
        const float4* v4 = (const float4*)(sV + m*8);
        float4 va = v4[0], vb = v4[1];
        A.x = fmaf(e, va.x, A.x); A.y = fmaf(e, va.y, A.y);
        A.z = fmaf(e, va.z, A.z); A.w = fmaf(e, va.w, A.w);
        B.x = fmaf(e, vb.x, B.x); B.y = fmaf(e, vb.y, B.y);
        B.z = fmaf(e, vb.z, B.z); B.w = fmaf(e, vb.w, B.w);
    }
    #pragma unroll
    for (int o = 16; o >= 4; o >>= 1) {     // reduce over kg bits only
        sum += __shfl_xor_sync(0xffffffffu, sum, o);
        A.x += __shfl_xor_sync(0xffffffffu, A.x, o);
        A.y += __shfl_xor_sync(0xffffffffu, A.y, o);
        A.z += __shfl_xor_sync(0xffffffffu, A.z, o);
        A.w += __shfl_xor_sync(0xffffffffu, A.w, o);
        B.x += __shfl_xor_sync(0xffffffffu, B.x, o);
        B.y += __shfl_xor_sync(0xffffffffu, B.y, o);
        B.z += __shfl_xor_sync(0xffffffffu, B.z, o);
        B.w += __shfl_xor_sync(0xffffffffu, B.w, o);
    }
    if (kg == 0) {
        const float inv = 1.f / sum;
        float4* dst = (float4*)(g_fo + (b*NPATCH + qi)*HID);
        dst[0] = make_float4(A.x*inv, A.y*inv, A.z*inv, A.w*inv);
        dst[1] = make_float4(B.x*inv, B.y*inv, B.z*inv, B.w*inv);
    }
}

// ---------------- stage 1 fused: projections + attention + LN + sigma head --
__global__ void attn1_kernel(const float* __restrict__ Wsq, const float* __restrict__ bsq,
                             const float* __restrict__ Wsk, const float* __restrict__ bsk,
                             const float* __restrict__ Wsv, const float* __restrict__ bsv,
                             const float* __restrict__ ln_g, const float* __restrict__ ln_b,
                             const float* __restrict__ Wp,   const float* __restrict__ bp) {
    __shared__ float sW[3][72];                 // 64 weights + 8 bias each
    __shared__ __align__(16) float sQ[32*8];
    __shared__ __align__(16) float sK[NPATCH*8];
    __shared__ __align__(16) float sV[NPATCH*8];
    const int b = blockIdx.y;
    const int tid = threadIdx.x;

    if (tid < 64) {
        sW[0][tid] = Wsq[tid]; sW[1][tid] = Wsk[tid]; sW[2][tid] = Wsv[tid];
    } else if (tid < 72) {
        int j = tid - 64;
        sW[0][64+j] = bsq[j]; sW[1][64+j] = bsk[j]; sW[2][64+j] = bsv[j];
    }
    __syncthreads();

    for (int t = tid; t < 32 + 2*NPATCH; t += 256) {
        int mode, slot, patch;
        if (t < 32)              { mode = 0; slot = t;             patch = blockIdx.x*32 + t; }
        else if (t < 32+NPATCH)  { mode = 1; slot = t - 32;        patch = slot; }
        else                     { mode = 2; slot = t - 32-NPATCH; patch = slot; }
        const float4* f4 = (const float4*)(g_fo + (b*NPATCH + patch)*HID);
        const float4 fa = f4[0], fb = f4[1];
        const float fo[HID] = {fa.x, fa.y, fa.z, fa.w, fb.x, fb.y, fb.z, fb.w};
        const float* W = sW[mode];
        float o[HID];
        #pragma unroll
        for (int j = 0; j < HID; j++) o[j] = W[64 + j];
        #pragma unroll
        for (int i = 0; i < HID; i++) {
            const float f = fo[i];
            #pragma unroll
            for (int j = 0; j < HID; j++) o[j] = fmaf(f, W[i*HID + j], o[j]);
        }
        const float sc = (mode == 0) ? SCALE : 1.f;
        float* dst = (mode == 0) ? (sQ + slot*8) : (mode == 1) ? (sK + slot*8) : (sV + slot*8);
        ((float4*)dst)[0] = make_float4(o[0]*sc, o[1]*sc, o[2]*sc, o[3]*sc);
        ((float4*)dst)[1] = make_float4(o[4]*sc, o[5]*sc, o[6]*sc, o[7]*sc);
    }
    __syncthreads();

    const int w = tid >> 5, lane = tid & 31;
    const int kg = lane >> 2, qq = lane & 3;
    const int qr = w*4 + qq;

    const float4* q4 = (const float4*)(sQ + qr*8);
    const float4 qa = q4[0], qb = q4[1];

    float sum = 0.f;
    float4 A = {0,0,0,0}, B = {0,0,0,0};
    #pragma unroll 8
    for (int i = 0; i < NPATCH/8; i++) {
        const int m = i*8 + kg;
        const float4* k4 = (const float4*)(sK + m*8);
        float4 ka = k4[0], kb = k4[1];
        float d = qa.x*ka.x;
        d = fmaf(qa.y, ka.y, d); d = fmaf(qa.z, ka.z, d); d = fmaf(qa.w, ka.w, d);
        d = fmaf(qb.x, kb.x, d); d = fmaf(qb.y, kb.y, d);
        d = fmaf(qb.z, kb.z, d); d = fmaf(qb.w, kb.w, d);
        const float e = __expf(d);
        sum += e;
        const float4* v4 = (const float4*)(sV + m*8);
        float4 va = v4[0], vb = v4[1];
        A.x = fmaf(e, va.x, A.x); A.y = fmaf(e, va.y, A.y);
        A.z = fmaf(e, va.z, A.z); A.w = fmaf(e, va.w, A.w);
        B.x = fmaf(e, vb.x, B.x); B.y = fmaf(e, vb.y, B.y);
        B.z = fmaf(e, vb.z, B.z); B.w = fmaf(e, vb.w, B.w);
    }
    #pragma unroll
    for (int o = 16; o >= 4; o >>= 1) {
        sum += __shfl_xor_sync(0xffffffffu, sum, o);
        A.x += __shfl_xor_sync(0xffffffffu, A.x, o);
        A.y += __shfl_xor_sync(0xffffffffu, A.y, o);
        A.z += __shfl_xor_sync(0xffffffffu, A.z, o);
        A.w += __shfl_xor_sync(0xffffffffu, A.w, o);
        B.x += __shfl_xor_sync(0xffffffffu, B.x, o);
        B.y += __shfl_xor_sync(0xffffffffu, B.y, o);
        B.z += __shfl_xor_sync(0xffffffffu, B.z, o);
        B.w += __shfl_xor_sync(0xffffffffu, B.w, o);
    }
    if (kg == 0) {
        const float inv = 1.f / sum;
        float fo[HID] = {A.x*inv, A.y*inv, A.z*inv, A.w*inv,
                         B.x*inv, B.y*inv, B.z*inv, B.w*inv};
        float mu = 0.f;
        #pragma unroll
        for (int j = 0; j < HID; j++) mu += fo[j];
        mu *= 0.125f;
        float var = 0.f;
        #pragma unroll
        for (int j = 0; j < HID; j++) { float d = fo[j]-mu; var = fmaf(d,d,var); }
        var *= 0.125f;
        const float rstd = rsqrtf(var + 1e-5f);
        float oin[HID];
        #pragma unroll
        for (int j = 0; j < HID; j++) oin[j] = (fo[j]-mu)*rstd*ln_g[j] + ln_b[j];
        const int qi = blockIdx.x*32 + qr;
        float sig[3];
        #pragma unroll
        for (int j = 0; j < 3; j++) {
            float sv = bp[j];
            #pragma unroll
            for (int i = 0; i < HID; i++) sv = fmaf(oin[i], Wp[i*3 + j], sv);
            float spv = (sv > 20.f) ? sv : log1pf(expf(sv));
            sig[j] = fminf(spv, 6.0f) + 1e-6f;
            g_s[(b*NPATCH + qi)*3 + j] = sig[j];
        }
        const float mx = fmaxf(sig[0], sig[1]);
        atomicMax(&g_max, __float_as_int(mx));   // positive floats: int order ok
    }
}

// ---------------- bilateral: separable moment method -------------------------
// wsum = sum_m a_m(c) S_m, acc = sum_m a_m(c) S_{m+1},  S_m = sum sp * p^m
// sp separable -> S_m via horizontal+vertical Gaussian passes. S_0 constant.
template<int K>
__device__ __forceinline__ void bilat_core2(
    const float* __restrict__ tE, const float* __restrict__ tO,
    u64* __restrict__ sM2,
    const u64* __restrict__ sex2, const u64* __restrict__ sey2,
    const float* __restrict__ sS0,
    int tid, float c1c, float c2c, float* __restrict__ outrow)
{
    constexpr int HALF = (K-1)/2;
    constexpr int T = PS + 2*HALF;

    // ---- horizontal: moments m1..m5 per (row, column-pair) ----
    for (int i = tid; i < 8*T; i += 256) {
        const int row = i >> 3, pr = i & 7;
        const int colb = pr*2;
        const float* eB = tE + row*TSTR + colb;
        const float* oB = tO + row*TSTR + colb;
        u64 m1=0ull, m2=0ull, m3=0ull, m4=0ull, m5=0ull;
        #pragma unroll
        for (int dx = 0; dx < K; dx++) {
            const u64 p2 = (dx & 1) ? *(const u64*)(oB + dx - 1)
                                    : *(const u64*)(eB + dx);
            const u64 e2 = sex2[dx];
            u64 t = mul2_(e2, p2);
            m1 = add2_(m1, t);
            t = mul2_(t, p2); m2 = add2_(m2, t);
            t = mul2_(t, p2); m3 = add2_(m3, t);
            t = mul2_(t, p2); m4 = add2_(m4, t);
            t = mul2_(t, p2); m5 = add2_(m5, t);
        }
        u64* d = sM2 + row*MSTR + pr*5;
        d[0] = m1; d[1] = m2; d[2] = m3; d[3] = m4; d[4] = m5;
    }
    __syncthreads();
    if (tid >= 128) return;

    // ---- vertical: S1..S5 per pixel pair ----
    const int r = tid >> 3, pr = tid & 7;
    u64 S1=0ull, S2=0ull, S3=0ull, S4=0ull, S5=0ull;
    #pragma unroll
    for (int dy = 0; dy < K; dy++) {
        const u64 ey2 = sey2[dy];
        const u64* mr = sM2 + (r + dy)*MSTR + pr*5;
        S1 = fma2_(ey2, mr[0], S1);
        S2 = fma2_(ey2, mr[1], S2);
        S3 = fma2_(ey2, mr[2], S3);
        S4 = fma2_(ey2, mr[3], S4);
        S5 = fma2_(ey2, mr[4], S5);
    }

    // ---- combine: polynomial coefficients from center values (packed) ----
    const int col = pr*2 + HALF;
    const u64 c2v = (HALF & 1) ? *(const u64*)(tO + (r+HALF)*TSTR + col - 1)
                               : *(const u64*)(tE + (r+HALF)*TSTR + col);
    const u64 C1v  = pk2(c1c, c1c);
    const u64 C2v  = pk2(c2c, c2c);
    const u64 ONE2 = pk2(1.f, 1.f);
    const u64 cc2 = mul2_(c2v, c2v);
    const u64 cc4 = mul2_(cc2, cc2);
    const u64 a0 = fma2_(C2v, cc4, fma2_(C1v, cc2, ONE2));
    const u64 t1 = fma2_(pk2(2.f*c2c, 2.f*c2c), cc2, C1v);
    const u64 a1 = mul2_(mul2_(pk2(-2.f,-2.f), c2v), t1);
    const u64 a2 = fma2_(pk2(6.f*c2c, 6.f*c2c), cc2, C1v);
    const u64 a3 = mul2_(pk2(-4.f*c2c, -4.f*c2c), c2v);
    const float s0 = *sS0;
    const u64 S0v = pk2(s0, s0);
    u64 ws = mul2_(a0, S0v);
    ws = fma2_(a1, S1, ws);
    ws = fma2_(a2, S2, ws);
    ws = fma2_(a3, S3, ws);
    ws = fma2_(C2v, S4, ws);
    u64 ac = mul2_(a0, S1);
    ac = fma2_(a1, S2, ac);
    ac = fma2_(a2, S3, ac);
    ac = fma2_(a3, S4, ac);
    ac = fma2_(C2v, S5, ac);
    const float2 wv = upk2(ws), av = upk2(ac);
    float2 res;
    res.x = av.x / (wv.x + 1e-8f);
    res.y = av.y / (wv.y + 1e-8f);
    *(float2*)(outrow + r*HW + pr*2) = res;
}

__global__ void bilateral_kernel(const float* __restrict__ x, float* __restrict__ out) {
    __shared__ __align__(16) float tE[32*TSTR];
    __shared__ __align__(16) float tO[32*TSTR];
    __shared__ u64 sM2[32*MSTR];
    __shared__ u64 sex2[20], sey2[20];
    __shared__ float sS0;
    const int n = blockIdx.x, b = blockIdx.y;
    const int hp = n / GRIDP, wn = n % GRIDP;
    const int tid = threadIdx.x;

    const float m = __int_as_float(g_max);
    const int half = (int)ceilf(m + 1.0f);
    const int k = 2*half + 1;

    const float* sv = g_s + (b*NPATCH + n)*3;
    const float sx = sv[0], sy = sv[1], sr = sv[2];
    const float ix = -0.5f/(sx*sx), iy = -0.5f/(sy*sy), ir = -0.5f/(sr*sr);
    const float c1c = ir, c2c = 0.5f*ir*ir;

    // stage tile with zero padding (stride TSTR); tO = tile shifted by 1
    const int y0 = hp*PS - half, x0 = wn*PS - half;
    const float* xb = x + b*HW*HW;
    for (int i = tid; i < 1024; i += 256) {
        const int ty = i >> 5, tx = i & 31;
        const int gy = y0 + ty, gx = x0 + tx;
        float v = 0.f;
        if ((unsigned)gy < HW && (unsigned)gx < HW && ty < 2*half+PS && tx < 2*half+PS)
            v = xb[gy*HW + gx];
        tE[ty*TSTR + tx] = v;
        if (tx > 0) tO[ty*TSTR + tx - 1] = v;
    }
    if (tid < k) {
        const float f = (float)(tid - half);
        const float ex = __expf(f*f*ix);
        const float ey = __expf(f*f*iy);
        sex2[tid] = pk2(ex, ex);
        sey2[tid] = pk2(ey, ey);
    }
    __syncthreads();
    if (tid == 0) {
        float se = 0.f, sy2 = 0.f;
        for (int i = 0; i < k; i++) {
            se  += upk2(sex2[i]).x;
            sy2 += upk2(sey2[i]).x;
        }
        sS0 = se * sy2;
    }

    float* outrow = out + (b*HW + hp*PS)*HW + wn*PS;
    switch (k) {
        case 3:  bilat_core2<3 >(tE, tO, sM2, sex2, sey2, &sS0, tid, c1c, c2c, outrow); break;
        case 5:  bilat_core2<5 >(tE, tO, sM2, sex2, sey2, &sS0, tid, c1c, c2c, outrow); break;
        case 7:  bilat_core2<7 >(tE, tO, sM2, sex2, sey2, &sS0, tid, c1c, c2c, outrow); break;
        case 9:  bilat_core2<9 >(tE, tO, sM2, sex2, sey2, &sS0, tid, c1c, c2c, outrow); break;
        case 11: bilat_core2<11>(tE, tO, sM2, sex2, sey2, &sS0, tid, c1c, c2c, outrow); break;
        case 13: bilat_core2<13>(tE, tO, sM2, sex2, sey2, &sS0, tid, c1c, c2c, outrow); break;
        case 15: bilat_core2<15>(tE, tO, sM2, sex2, sey2, &sS0, tid, c1c, c2c, outrow); break;
        case 17: bilat_core2<17>(tE, tO, sM2, sex2, sey2, &sS0, tid, c1c, c2c, outrow); break;
        default: {   // generic fallback (unreachable: sigma cap bounds k <= 17)
            const int r = tid >> 4, cc = tid & 15;
            const float c = tE[(r + half)*TSTR + cc + half];
            float acc = 0.f, wsum = 0.f;
            for (int dy = 0; dy < k; dy++) {
                const float fy = (float)(dy - half);
                const float ey = __expf(fy*fy*iy);
                const float* trow = tE + (r + dy)*TSTR + cc;
                for (int dx = 0; dx < k; dx++) {
                    const float fx = (float)(dx - half);
                    const float p = trow[dx];
                    const float d = c - p;
                    const float w = ey * __expf(fx*fx*ix) * __expf(d*d*ir);
                    wsum += w;
                    acc = fmaf(w, p, acc);
                }
            }
            outrow[r*HW + cc] = acc / (wsum + 1e-8f);
        }
    }
}

// ---------------- launcher ---------------------------------------------------
extern "C" void kernel_launch(void* const* d_in, const int* in_sizes, int n_in,
                              void* d_out, int out_size) {
    const float* x    = (const float*)d_in[0];
    const float* Wq   = (const float*)d_in[1];
    const float* bq   = (const float*)d_in[2];
    const float* Wk   = (const float*)d_in[3];
    const float* bk   = (const float*)d_in[4];
    const float* Wv   = (const float*)d_in[5];
    const float* bv   = (const float*)d_in[6];
    const float* Wsq  = (const float*)d_in[7];
    const float* bsq  = (const float*)d_in[8];
    const float* Wsk  = (const float*)d_in[9];
    const float* bsk  = (const float*)d_in[10];
    const float* Wsv  = (const float*)d_in[11];
    const float* bsv  = (const float*)d_in[12];
    const float* ln_g = (const float*)d_in[13];
    const float* ln_b = (const float*)d_in[14];
    const float* Wp   = (const float*)d_in[15];
    const float* bp   = (const float*)d_in[16];
    float* out = (float*)d_out;

    qkv_kernel<<<dim3(NPATCH/4, NB), 256>>>(x, Wq, bq, Wk, bk, Wv, bv);
    attn0_kernel<<<dim3(NPATCH/32, NB), 256>>>();
    attn1_kernel<<<dim3(NPATCH/32, NB), 256>>>(Wsq, bsq, Wsk, bsk, Wsv, bsv,
                                               ln_g, ln_b, Wp, bp);
    bilateral_kernel<<<dim3(NPATCH, NB), 256>>>(x, out);
}

// round 8
// speedup vs baseline: 2.2182x; 1.1191x over previous
#include <cuda_runtime.h>
#include <math.h>

#define PS    16
#define HID   8
#define GRIDP 24
#define NPATCH 576      // 24*24
#define NB    2
#define HW    384
#define DIN   256
#define SCALE 0.35355339059327373f

#define TSTR  48        // tile row stride (floats)
#define MSTR  48        // moment row stride (u64): 8 slots x 6 u64

typedef unsigned long long u64;

// ---------------- scratch (device globals; no allocation allowed) ----------
__device__ float g_q1[NB*NPATCH*HID];
__device__ float g_k1[NB*NPATCH*HID];
__device__ float g_v1[NB*NPATCH*HID];
__device__ float g_q2[NB*NPATCH*HID];    // pre-scaled by SCALE
__device__ float g_k2[NB*NPATCH*HID];
__device__ float g_v2[NB*NPATCH*HID];
__device__ float g_s [NB*NPATCH*3];
__device__ int   g_max;

// ---------------- packed f32x2 helpers (Blackwell) --------------------------
__device__ __forceinline__ u64 pk2(float lo, float hi){
    u64 r; asm("mov.b64 %0, {%1, %2};" : "=l"(r) : "f"(lo), "f"(hi)); return r;
}
__device__ __forceinline__ float2 upk2(u64 v){
    float2 f; asm("mov.b64 {%0, %1}, %2;" : "=f"(f.x), "=f"(f.y) : "l"(v)); return f;
}
__device__ __forceinline__ u64 fma2_(u64 a, u64 b, u64 c){
    u64 d; asm("fma.rn.f32x2 %0, %1, %2, %3;" : "=l"(d) : "l"(a), "l"(b), "l"(c)); return d;
}
__device__ __forceinline__ u64 mul2_(u64 a, u64 b){
    u64 d; asm("mul.rn.f32x2 %0, %1, %2;" : "=l"(d) : "l"(a), "l"(b)); return d;
}
__device__ __forceinline__ u64 add2_(u64 a, u64 b){
    u64 d; asm("add.rn.f32x2 %0, %1, %2;" : "=l"(d) : "l"(a), "l"(b)); return d;
}

// ---------------- qkv: 8 patches/block, smem-staged transposed W ------------
__global__ void qkv_kernel(const float* __restrict__ x,
                           const float* __restrict__ Wq, const float* __restrict__ bq,
                           const float* __restrict__ Wk, const float* __restrict__ bk,
                           const float* __restrict__ Wv, const float* __restrict__ bv) {
    __shared__ float sWq[DIN*9], sWk[DIN*9], sWv[DIN*9];   // [i*9 + col], pad 9
    __shared__ float sPat[8][DIN];
    const int n0 = blockIdx.x * 8, b = blockIdx.y;
    const int tid = threadIdx.x;
    if (blockIdx.x == 0 && b == 0 && tid == 0) g_max = 0;  // fold init

    #pragma unroll
    for (int e = tid; e < DIN*HID; e += 256) {
        int idx = (e >> 3)*9 + (e & 7);
        sWq[idx] = Wq[e]; sWk[idx] = Wk[e]; sWv[idx] = Wv[e];
    }
    const int r = tid >> 4, cc = tid & 15;
    #pragma unroll
    for (int p = 0; p < 8; p++) {
        int n = n0 + p;
        int hp = n / GRIDP, wn = n % GRIDP;
        sPat[p][tid] = x[(b*HW + hp*PS + r)*HW + wn*PS + cc];
    }
    __syncthreads();

    const int w = tid >> 5, lane = tid & 31;
    float aq[8], ak[8], av[8];
    #pragma unroll
    for (int p = 0; p < 8; p++) { aq[p] = 0.f; ak[p] = 0.f; av[p] = 0.f; }
    #pragma unroll
    for (int it = 0; it < DIN/32; ++it) {
        const int i = lane + 32*it;
        const float wq = sWq[i*9 + w], wk = sWk[i*9 + w], wv = sWv[i*9 + w];
        #pragma unroll
        for (int p = 0; p < 8; p++) {
            const float pv = sPat[p][i];
            aq[p] = fmaf(pv, wq, aq[p]);
            ak[p] = fmaf(pv, wk, ak[p]);
            av[p] = fmaf(pv, wv, av[p]);
        }
    }
    #pragma unroll
    for (int o = 16; o; o >>= 1) {
        #pragma unroll
        for (int p = 0; p < 8; p++) {
            aq[p] += __shfl_xor_sync(0xffffffffu, aq[p], o);
            ak[p] += __shfl_xor_sync(0xffffffffu, ak[p], o);
            av[p] += __shfl_xor_sync(0xffffffffu, av[p], o);
        }
    }
    if (lane < 8) {
        const int p = lane;
        const int base = (b*NPATCH + n0 + p)*HID + w;
        g_q1[base] = aq[p] + bq[w];
        g_k1[base] = ak[p] + bk[w];
        g_v1[base] = av[p] + bv[w];
    }
}

// ---------------- attention stage 0 + projection epilogue --------------------
// grid (36, 2), 256 threads. lane = (kg 0..15, qq 0..1): 2 queries/warp.
__global__ void attn0_kernel(const float* __restrict__ Wsq, const float* __restrict__ bsq,
                             const float* __restrict__ Wsk, const float* __restrict__ bsk,
                             const float* __restrict__ Wsv, const float* __restrict__ bsv) {
    __shared__ float sW[3][72];                 // 64 weights + 8 bias each
    __shared__ __align__(16) float sK[NPATCH*8];
    __shared__ __align__(16) float sV[NPATCH*8];
    const int b = blockIdx.y;
    const int tid = threadIdx.x;

    if (tid < 64) {
        sW[0][tid] = Wsq[tid]; sW[1][tid] = Wsk[tid]; sW[2][tid] = Wsv[tid];
    } else if (tid < 72) {
        int j = tid - 64;
        sW[0][64+j] = bsq[j]; sW[1][64+j] = bsk[j]; sW[2][64+j] = bsv[j];
    }
    const float4* k4g = (const float4*)(g_k1 + b*NPATCH*HID);
    const float4* v4g = (const float4*)(g_v1 + b*NPATCH*HID);
    #pragma unroll
    for (int t = tid; t < NPATCH*2; t += 256) {
        ((float4*)sK)[t] = k4g[t];
        ((float4*)sV)[t] = v4g[t];
    }
    __syncthreads();

    const int w = tid >> 5, lane = tid & 31;
    const int kg = lane >> 1, qq = lane & 1;
    const int qi = blockIdx.x*16 + w*2 + qq;

    const float4* q4 = (const float4*)(g_q1 + (b*NPATCH + qi)*HID);
    float4 qa = q4[0], qb = q4[1];
    qa.x *= SCALE; qa.y *= SCALE; qa.z *= SCALE; qa.w *= SCALE;
    qb.x *= SCALE; qb.y *= SCALE; qb.z *= SCALE; qb.w *= SCALE;

    float sum = 0.f;
    float4 A = {0,0,0,0}, B = {0,0,0,0};
    #pragma unroll 6
    for (int i = 0; i < NPATCH/16; i++) {
        const int m = i*16 + kg;
        const float4* k4 = (const float4*)(sK + m*8);
        float4 ka = k4[0], kb = k4[1];
        float d = qa.x*ka.x;
        d = fmaf(qa.y, ka.y, d); d = fmaf(qa.z, ka.z, d); d = fmaf(qa.w, ka.w, d);
        d = fmaf(qb.x, kb.x, d); d = fmaf(qb.y, kb.y, d);
        d = fmaf(qb.z, kb.z, d); d = fmaf(qb.w, kb.w, d);
        const float e = __expf(d);
        sum += e;
        const float4* v4 = (const float4*)(sV + m*8);
        float4 va = v4[0], vb = v4[1];
        A.x = fmaf(e, va.x, A.x); A.y = fmaf(e, va.y, A.y);
        A.z = fmaf(e, va.z, A.z); A.w = fmaf(e, va.w, A.w);
        B.x = fmaf(e, vb.x, B.x); B.y = fmaf(e, vb.y, B.y);
        B.z = fmaf(e, vb.z, B.z); B.w = fmaf(e, vb.w, B.w);
    }
    #pragma unroll
    for (int o = 16; o >= 2; o >>= 1) {     // reduce over kg bits only
        sum += __shfl_xor_sync(0xffffffffu, sum, o);
        A.x += __shfl_xor_sync(0xffffffffu, A.x, o);
        A.y += __shfl_xor_sync(0xffffffffu, A.y, o);
        A.z += __shfl_xor_sync(0xffffffffu, A.z, o);
        A.w += __shfl_xor_sync(0xffffffffu, A.w, o);
        B.x += __shfl_xor_sync(0xffffffffu, B.x, o);
        B.y += __shfl_xor_sync(0xffffffffu, B.y, o);
        B.z += __shfl_xor_sync(0xffffffffu, B.z, o);
        B.w += __shfl_xor_sync(0xffffffffu, B.w, o);
    }
    if (kg == 0) {
        const float inv = 1.f / sum;
        const float fo[HID] = {A.x*inv, A.y*inv, A.z*inv, A.w*inv,
                               B.x*inv, B.y*inv, B.z*inv, B.w*inv};
        const int base = (b*NPATCH + qi)*HID;
        #pragma unroll
        for (int mode = 0; mode < 3; mode++) {
            const float* W = sW[mode];
            float o[HID];
            #pragma unroll
            for (int j = 0; j < HID; j++) o[j] = W[64 + j];
            #pragma unroll
            for (int i = 0; i < HID; i++) {
                const float f = fo[i];
                #pragma unroll
                for (int j = 0; j < HID; j++) o[j] = fmaf(f, W[i*HID + j], o[j]);
            }
            float* dst = (mode == 0) ? (g_q2 + base) : (mode == 1) ? (g_k2 + base) : (g_v2 + base);
            const float sc = (mode == 0) ? SCALE : 1.f;
            ((float4*)dst)[0] = make_float4(o[0]*sc, o[1]*sc, o[2]*sc, o[3]*sc);
            ((float4*)dst)[1] = make_float4(o[4]*sc, o[5]*sc, o[6]*sc, o[7]*sc);
        }
    }
}

// ---------------- attention stage 1 + LN + sigma head ------------------------
// grid (36, 2), 256 threads. 2 queries/warp; K/V staged from g_k2/g_v2.
__global__ void attn1_kernel(const float* __restrict__ ln_g, const float* __restrict__ ln_b,
                             const float* __restrict__ Wp,   const float* __restrict__ bp) {
    __shared__ __align__(16) float sQ[16*8];
    __shared__ __align__(16) float sK[NPATCH*8];
    __shared__ __align__(16) float sV[NPATCH*8];
    const int b = blockIdx.y;
    const int tid = threadIdx.x;

    if (tid < 32)
        ((float4*)sQ)[tid] = ((const float4*)(g_q2 + (b*NPATCH + blockIdx.x*16)*HID))[tid];
    const float4* k4g = (const float4*)(g_k2 + b*NPATCH*HID);
    const float4* v4g = (const float4*)(g_v2 + b*NPATCH*HID);
    #pragma unroll
    for (int t = tid; t < NPATCH*2; t += 256) {
        ((float4*)sK)[t] = k4g[t];
        ((float4*)sV)[t] = v4g[t];
    }
    __syncthreads();

    const int w = tid >> 5, lane = tid & 31;
    const int kg = lane >> 1, qq = lane & 1;
    const int qr = w*2 + qq;

    const float4* q4 = (const float4*)(sQ + qr*8);
    const float4 qa = q4[0], qb = q4[1];

    float sum = 0.f;
    float4 A = {0,0,0,0}, B = {0,0,0,0};
    #pragma unroll 6
    for (int i = 0; i < NPATCH/16; i++) {
        const int m = i*16 + kg;
        const float4* k4 = (const float4*)(sK + m*8);
        float4 ka = k4[0], kb = k4[1];
        float d = qa.x*ka.x;
        d = fmaf(qa.y, ka.y, d); d = fmaf(qa.z, ka.z, d); d = fmaf(qa.w, ka.w, d);
        d = fmaf(qb.x, kb.x, d); d = fmaf(qb.y, kb.y, d);
        d = fmaf(qb.z, kb.z, d); d = fmaf(qb.w, kb.w, d);
        const float e = __expf(d);
        sum += e;
        const float4* v4 = (const float4*)(sV + m*8);
        float4 va = v4[0], vb = v4[1];
        A.x = fmaf(e, va.x, A.x); A.y = fmaf(e, va.y, A.y);
        A.z = fmaf(e, va.z, A.z); A.w = fmaf(e, va.w, A.w);
        B.x = fmaf(e, vb.x, B.x); B.y = fmaf(e, vb.y, B.y);
        B.z = fmaf(e, vb.z, B.z); B.w = fmaf(e, vb.w, B.w);
    }
    #pragma unroll
    for (int o = 16; o >= 2; o >>= 1) {
        sum += __shfl_xor_sync(0xffffffffu, sum, o);
        A.x += __shfl_xor_sync(0xffffffffu, A.x, o);
        A.y += __shfl_xor_sync(0xffffffffu, A.y, o);
        A.z += __shfl_xor_sync(0xffffffffu, A.z, o);
        A.w += __shfl_xor_sync(0xffffffffu, A.w, o);
        B.x += __shfl_xor_sync(0xffffffffu, B.x, o);
        B.y += __shfl_xor_sync(0xffffffffu, B.y, o);
        B.z += __shfl_xor_sync(0xffffffffu, B.z, o);
        B.w += __shfl_xor_sync(0xffffffffu, B.w, o);
    }
    if (kg == 0) {
        const float inv = 1.f / sum;
        float fo[HID] = {A.x*inv, A.y*inv, A.z*inv, A.w*inv,
                         B.x*inv, B.y*inv, B.z*inv, B.w*inv};
        float mu = 0.f;
        #pragma unroll
        for (int j = 0; j < HID; j++) mu += fo[j];
        mu *= 0.125f;
        float var = 0.f;
        #pragma unroll
        for (int j = 0; j < HID; j++) { float d = fo[j]-mu; var = fmaf(d,d,var); }
        var *= 0.125f;
        const float rstd = rsqrtf(var + 1e-5f);
        float oin[HID];
        #pragma unroll
        for (int j = 0; j < HID; j++) oin[j] = (fo[j]-mu)*rstd*ln_g[j] + ln_b[j];
        const int qi = blockIdx.x*16 + qr;
        float sig[3];
        #pragma unroll
        for (int j = 0; j < 3; j++) {
            float sv = bp[j];
            #pragma unroll
            for (int i = 0; i < HID; i++) sv = fmaf(oin[i], Wp[i*3 + j], sv);
            float spv = (sv > 20.f) ? sv : log1pf(expf(sv));
            sig[j] = fminf(spv, 6.0f) + 1e-6f;
            g_s[(b*NPATCH + qi)*3 + j] = sig[j];
        }
        const float mx = fmaxf(sig[0], sig[1]);
        atomicMax(&g_max, __float_as_int(mx));   // positive floats: int order ok
    }
}

// ---------------- bilateral: separable moment method -------------------------
// Moment slots: 6 u64 (48B, 16B-aligned) -> conflict-free LDS.128 vertical.
template<int K>
__device__ __forceinline__ void bilat_core2(
    const float* __restrict__ tE, const float* __restrict__ tO,
    u64* __restrict__ sM2,
    const u64* __restrict__ sex2, const u64* __restrict__ sey2,
    const float* __restrict__ sS0,
    int tid, float c1c, float c2c, float* __restrict__ outrow)
{
    constexpr int HALF = (K-1)/2;
    constexpr int T = PS + 2*HALF;     // <= 32

    // ---- horizontal: moments m1..m5 per (row, column-pair); one point/thread
    if (tid < 8*T) {
        const int row = tid >> 3, pr = tid & 7;
        const int colb = pr*2;
        const float* eB = tE + row*TSTR + colb;
        const float* oB = tO + row*TSTR + colb;
        u64 m1=0ull, m2=0ull, m3=0ull, m4=0ull, m5=0ull;
        #pragma unroll
        for (int dx = 0; dx < K; dx++) {
            const u64 p2 = (dx & 1) ? *(const u64*)(oB + dx - 1)
                                    : *(const u64*)(eB + dx);
            const u64 e2 = sex2[dx];
            u64 t = mul2_(e2, p2);
            m1 = add2_(m1, t);
            t = mul2_(t, p2); m2 = add2_(m2, t);
            t = mul2_(t, p2); m3 = add2_(m3, t);
            t = mul2_(t, p2); m4 = add2_(m4, t);
            t = mul2_(t, p2); m5 = add2_(m5, t);
        }
        u64* d = sM2 + row*MSTR + pr*6;
        ((ulonglong2*)d)[0] = make_ulonglong2(m1, m2);
        ((ulonglong2*)d)[1] = make_ulonglong2(m3, m4);
        ((ulonglong2*)d)[2] = make_ulonglong2(m5, m5);
    }
    __syncthreads();
    if (tid >= 128) return;

    // ---- vertical: S1..S5 per pixel pair (conflict-free LDS.128) ----
    const int r = tid >> 3, pr = tid & 7;
    u64 S1=0ull, S2=0ull, S3=0ull, S4=0ull, S5=0ull;
    #pragma unroll
    for (int dy = 0; dy < K; dy++) {
        const u64 ey2 = sey2[dy];
        const u64* mr = sM2 + (r + dy)*MSTR + pr*6;
        const ulonglong2 L0 = ((const ulonglong2*)mr)[0];
        const ulonglong2 L1 = ((const ulonglong2*)mr)[1];
        const u64 m5 = mr[4];
        S1 = fma2_(ey2, L0.x, S1);
        S2 = fma2_(ey2, L0.y, S2);
        S3 = fma2_(ey2, L1.x, S3);
        S4 = fma2_(ey2, L1.y, S4);
        S5 = fma2_(ey2, m5,   S5);
    }

    // ---- combine: polynomial coefficients from center values (packed) ----
    const int col = pr*2 + HALF;
    const u64 c2v = (HALF & 1) ? *(const u64*)(tO + (r+HALF)*TSTR + col - 1)
                               : *(const u64*)(tE + (r+HALF)*TSTR + col);
    const u64 C1v  = pk2(c1c, c1c);
    const u64 C2v  = pk2(c2c, c2c);
    const u64 ONE2 = pk2(1.f, 1.f);
    const u64 cc2 = mul2_(c2v, c2v);
    const u64 cc4 = mul2_(cc2, cc2);
    const u64 a0 = fma2_(C2v, cc4, fma2_(C1v, cc2, ONE2));
    const u64 t1 = fma2_(pk2(2.f*c2c, 2.f*c2c), cc2, C1v);
    const u64 a1 = mul2_(mul2_(pk2(-2.f,-2.f), c2v), t1);
    const u64 a2 = fma2_(pk2(6.f*c2c, 6.f*c2c), cc2, C1v);
    const u64 a3 = mul2_(pk2(-4.f*c2c, -4.f*c2c), c2v);
    const float s0 = *sS0;
    const u64 S0v = pk2(s0, s0);
    u64 ws = mul2_(a0, S0v);
    ws = fma2_(a1, S1, ws);
    ws = fma2_(a2, S2, ws);
    ws = fma2_(a3, S3, ws);
    ws = fma2_(C2v, S4, ws);
    u64 ac = mul2_(a0, S1);
    ac = fma2_(a1, S2, ac);
    ac = fma2_(a2, S3, ac);
    ac = fma2_(a3, S4, ac);
    ac = fma2_(C2v, S5, ac);
    const float2 wv = upk2(ws), av = upk2(ac);
    float2 res;
    res.x = av.x / (wv.x + 1e-8f);
    res.y = av.y / (wv.y + 1e-8f);
    *(float2*)(outrow + r*HW + pr*2) = res;
}

__global__ void bilateral_kernel(const float* __restrict__ x, float* __restrict__ out) {
    __shared__ __align__(16) float tE[32*TSTR];
    __shared__ __align__(16) float tO[32*TSTR];
    __shared__ __align__(16) u64 sM2[32*MSTR];
    __shared__ u64 sex2[20], sey2[20];
    __shared__ float sS0;
    const int n = blockIdx.x, b = blockIdx.y;
    const int hp = n / GRIDP, wn = n % GRIDP;
    const int tid = threadIdx.x;

    const float m = __int_as_float(g_max);
    const int half = (int)ceilf(m + 1.0f);
    const int k = 2*half + 1;

    const float* sv = g_s + (b*NPATCH + n)*3;
    const float sx = sv[0], sy = sv[1], sr = sv[2];
    const float ix = -0.5f/(sx*sx), iy = -0.5f/(sy*sy), ir = -0.5f/(sr*sr);
    const float c1c = ir, c2c = 0.5f*ir*ir;

    // stage tile with zero padding (stride TSTR); tO = tile shifted by 1
    const int y0 = hp*PS - half, x0 = wn*PS - half;
    const float* xb = x + b*HW*HW;
    for (int i = tid; i < 1024; i += 256) {
        const int ty = i >> 5, tx = i & 31;
        const int gy = y0 + ty, gx = x0 + tx;
        float v = 0.f;
        if ((unsigned)gy < HW && (unsigned)gx < HW && ty < 2*half+PS && tx < 2*half+PS)
            v = xb[gy*HW + gx];
        tE[ty*TSTR + tx] = v;
        if (tx > 0) tO[ty*TSTR + tx - 1] = v;
    }
    if (tid < k) {
        const float f = (float)(tid - half);
        const float ex = __expf(f*f*ix);
        const float ey = __expf(f*f*iy);
        sex2[tid] = pk2(ex, ex);
        sey2[tid] = pk2(ey, ey);
    }
    __syncthreads();
    if (tid == 0) {
        float se = 0.f, sy2 = 0.f;
        for (int i = 0; i < k; i++) {
            se  += upk2(sex2[i]).x;
            sy2 += upk2(sey2[i]).x;
        }
        sS0 = se * sy2;
    }

    float* outrow = out + (b*HW + hp*PS)*HW + wn*PS;
    switch (k) {
        case 3:  bilat_core2<3 >(tE, tO, sM2, sex2, sey2, &sS0, tid, c1c, c2c, outrow); break;
        case 5:  bilat_core2<5 >(tE, tO, sM2, sex2, sey2, &sS0, tid, c1c, c2c, outrow); break;
        case 7:  bilat_core2<7 >(tE, tO, sM2, sex2, sey2, &sS0, tid, c1c, c2c, outrow); break;
        case 9:  bilat_core2<9 >(tE, tO, sM2, sex2, sey2, &sS0, tid, c1c, c2c, outrow); break;
        case 11: bilat_core2<11>(tE, tO, sM2, sex2, sey2, &sS0, tid, c1c, c2c, outrow); break;
        case 13: bilat_core2<13>(tE, tO, sM2, sex2, sey2, &sS0, tid, c1c, c2c, outrow); break;
        case 15: bilat_core2<15>(tE, tO, sM2, sex2, sey2, &sS0, tid, c1c, c2c, outrow); break;
        case 17: bilat_core2<17>(tE, tO, sM2, sex2, sey2, &sS0, tid, c1c, c2c, outrow); break;
        default: {   // generic fallback (unreachable: sigma cap bounds k <= 17)
            const int r = tid >> 4, cc = tid & 15;
            const float c = tE[(r + half)*TSTR + cc + half];
            float acc = 0.f, wsum = 0.f;
            for (int dy = 0; dy < k; dy++) {
                const float fy = (float)(dy - half);
                const float ey = __expf(fy*fy*iy);
                const float* trow = tE + (r + dy)*TSTR + cc;
                for (int dx = 0; dx < k; dx++) {
                    const float fx = (float)(dx - half);
                    const float p = trow[dx];
                    const float d = c - p;
                    const float w = ey * __expf(fx*fx*ix) * __expf(d*d*ir);
                    wsum += w;
                    acc = fmaf(w, p, acc);
                }
            }
            outrow[r*HW + cc] = acc / (wsum + 1e-8f);
        }
    }
}

// ---------------- launcher ---------------------------------------------------
extern "C" void kernel_launch(void* const* d_in, const int* in_sizes, int n_in,
                              void* d_out, int out_size) {
    const float* x    = (const float*)d_in[0];
    const float* Wq   = (const float*)d_in[1];
    const float* bq   = (const float*)d_in[2];
    const float* Wk   = (const float*)d_in[3];
    const float* bk   = (const float*)d_in[4];
    const float* Wv   = (const float*)d_in[5];
    const float* bv   = (const float*)d_in[6];
    const float* Wsq  = (const float*)d_in[7];
    const float* bsq  = (const float*)d_in[8];
    const float* Wsk  = (const float*)d_in[9];
    const float* bsk  = (const float*)d_in[10];
    const float* Wsv  = (const float*)d_in[11];
    const float* bsv  = (const float*)d_in[12];
    const float* ln_g = (const float*)d_in[13];
    const float* ln_b = (const float*)d_in[14];
    const float* Wp   = (const float*)d_in[15];
    const float* bp   = (const float*)d_in[16];
    float* out = (float*)d_out;

    qkv_kernel<<<dim3(NPATCH/8, NB), 256>>>(x, Wq, bq, Wk, bk, Wv, bv);
    attn0_kernel<<<dim3(NPATCH/16, NB), 256>>>(Wsq, bsq, Wsk, bsk, Wsv, bsv);
    attn1_kernel<<<dim3(NPATCH/16, NB), 256>>>(ln_g, ln_b, Wp, bp);
    bilateral_kernel<<<dim3(NPATCH, NB), 256>>>(x, out);
}